// round 5
// baseline (speedup 1.0000x reference)
#include <cuda_runtime.h>
#include <math.h>
#include <stdint.h>

#define B_   2
#define S_   2048
#define H_   2048
#define NH_  16
#define HD_  128
#define NE_  8
#define I_   4096
#define T_   (B_*S_)
#define EPS_ 1e-5f
#define ATT_SCALE 0.08838834764831845f

// -------------------- scratch --------------------
__device__ float g_xn [(size_t)T_*H_];
__device__ float g_q  [(size_t)T_*H_];
__device__ float g_k  [(size_t)T_*H_];
__device__ float g_v  [(size_t)T_*H_];
__device__ float g_att[(size_t)B_*NH_*S_*S_];
__device__ float g_ao [(size_t)T_*H_];
__device__ float g_xn2[(size_t)T_*H_];
__device__ float g_hg [(size_t)NE_*T_*I_];
__device__ float g_hu [(size_t)NE_*T_*I_];
__device__ int   g_tok[NE_*T_];
__device__ float g_wt [NE_*T_];
__device__ int   g_cnt[NE_];

// -------------------- helpers --------------------
__device__ __forceinline__ uint32_t f2tf(float f) {
    uint32_t r; asm("cvt.rna.tf32.f32 %0, %1;" : "=r"(r) : "f"(f)); return r;
}
__device__ __forceinline__ void mma8(float* c, const uint32_t* a, uint32_t b0, uint32_t b1) {
    asm volatile("mma.sync.aligned.m16n8k8.row.col.f32.tf32.tf32.f32 "
        "{%0,%1,%2,%3},{%4,%5,%6,%7},{%8,%9},{%0,%1,%2,%3};"
        : "+f"(c[0]), "+f"(c[1]), "+f"(c[2]), "+f"(c[3])
        : "r"(a[0]), "r"(a[1]), "r"(a[2]), "r"(a[3]), "r"(b0), "r"(b1));
}
__device__ __forceinline__ void ldsm4(uint32_t* r, uint32_t addr) {
    asm volatile("ldmatrix.sync.aligned.m8n8.x4.shared.b16 {%0,%1,%2,%3},[%4];"
        : "=r"(r[0]), "=r"(r[1]), "=r"(r[2]), "=r"(r[3]) : "r"(addr));
}
__device__ __forceinline__ void cpa16(uint32_t dst, const void* src) {
    asm volatile("cp.async.cg.shared.global [%0], [%1], 16;" :: "r"(dst), "l"(src));
}
__device__ __forceinline__ void cpa_commit() { asm volatile("cp.async.commit_group;"); }
__device__ __forceinline__ void cpa_wait0()  { asm volatile("cp.async.wait_group 0;" ::: "memory"); }
__device__ __forceinline__ void cpa_wait1()  { asm volatile("cp.async.wait_group 1;" ::: "memory"); }
__device__ __forceinline__ uint32_t smem_u32(const void* p) {
    uint32_t a; asm("{ .reg .u64 t; cvta.to.shared.u64 t, %1; cvt.u32.u64 %0, t; }"
                    : "=r"(a) : "l"(p));
    return a;
}
// round-half-away to tf32 by bumping raw fp32 bits (HMMA ignores low 13 bits)
#define RND_FRAG(r) { (r)[0]+=0x1000u; (r)[1]+=0x1000u; (r)[2]+=0x1000u; (r)[3]+=0x1000u; }

// -------------------- small kernels --------------------
__global__ void zero_cnt_k() { if (threadIdx.x < NE_) g_cnt[threadIdx.x] = 0; }

__global__ void rmsnorm_k(const float* __restrict__ x, const float* __restrict__ w,
                          float* __restrict__ o) {
    int t = blockIdx.x;
    const float* xr = x + (size_t)t * H_;
    float s = 0.f;
    for (int j = threadIdx.x; j < H_; j += blockDim.x) { float v = xr[j]; s += v * v; }
    __shared__ float red[32];
    for (int off = 16; off; off >>= 1) s += __shfl_xor_sync(0xffffffffu, s, off);
    if ((threadIdx.x & 31) == 0) red[threadIdx.x >> 5] = s;
    __syncthreads();
    if (threadIdx.x < 32) {
        float v = (threadIdx.x < (blockDim.x >> 5)) ? red[threadIdx.x] : 0.f;
        for (int off = 16; off; off >>= 1) v += __shfl_xor_sync(0xffffffffu, v, off);
        if (threadIdx.x == 0) red[0] = v;
    }
    __syncthreads();
    float inv = rsqrtf(red[0] / (float)H_ + EPS_);
    float* orow = o + (size_t)t * H_;
    for (int j = threadIdx.x; j < H_; j += blockDim.x) orow[j] = xr[j] * inv * w[j];
}

__global__ void swiglu_all_k(float* __restrict__ hg, const float* __restrict__ hu) {
    int e = blockIdx.y;
    int cnt = g_cnt[e];
    float4* G = (float4*)(hg + (size_t)e * T_ * I_);
    const float4* U = (const float4*)(hu + (size_t)e * T_ * I_);
    size_t total = (size_t)cnt * (I_ / 4);
    size_t stride = (size_t)gridDim.x * blockDim.x;
    for (size_t i = (size_t)blockIdx.x * blockDim.x + threadIdx.x; i < total; i += stride) {
        float4 g = G[i], u = U[i];
        g.x = g.x / (1.f + __expf(-g.x)) * u.x;
        g.y = g.y / (1.f + __expf(-g.y)) * u.y;
        g.z = g.z / (1.f + __expf(-g.z)) * u.z;
        g.w = g.w / (1.f + __expf(-g.w)) * u.w;
        G[i] = g;
    }
}

// ==================== tf32 MMA GEMM (2-stage cp.async + ldmatrix) ====================
// C[M,N] = A[M,K] * B[N,K]^T.
// Mode 0: z selects (B,C) among B0/C0,B1/C1,B2/C2. Optional resid: C = acc + resid.
// Mode 1: z = expert*2+{gate,up}; A rows gathered via token list; dense store.
// Mode 2: z = expert; dense A (per-expert hg); atomic scatter-add epilogue.
struct GArgs {
    const float* A;
    const float* B0; const float* B1; const float* B2;
    float* C0; float* C1; float* C2;
    const float* resid;
    int M, N, K, lda, ldb, ldc;
    const int* tok; const float* wt; const int* cntp;
    size_t aStride, bStride, cStride;
    int mode;
};

#define BK 32
#define SROW 36
#define SOFF (128*SROW*4)              // 18432 B per matrix-stage
#define SMEM_BYTES (4*SOFF)            // 73728 B (2 stages x A,B)
#define SMEM_BYTES3 (6*SOFF)           // 110592 B (3 stages, attn_score only)

__global__ void __launch_bounds__(256, 2)
mma_gemm2(const GArgs args) {
    int z = blockIdx.z;
    const float* A = args.A;
    const float* B;
    float* C;
    const int* a_idx = nullptr; const int* c_idx = nullptr; const float* c_w = nullptr;
    int cnt = args.M;
    bool atomic_ep = false;

    if (args.mode == 0) {
        B = (z == 0) ? args.B0 : (z == 1 ? args.B1 : args.B2);
        C = (z == 0) ? args.C0 : (z == 1 ? args.C1 : args.C2);
    } else if (args.mode == 1) {
        int e = z >> 1;
        B = ((z & 1) ? args.B1 : args.B0) + (size_t)e * args.bStride;
        C = ((z & 1) ? args.C1 : args.C0) + (size_t)e * args.cStride;
        a_idx = args.tok + e * T_;
        cnt = args.cntp[e];
    } else {
        int e = z;
        A = args.A + (size_t)e * args.aStride;
        B = args.B0 + (size_t)e * args.bStride;
        C = args.C0;
        c_idx = args.tok + e * T_;
        c_w = args.wt + e * T_;
        cnt = args.cntp[e];
        atomic_ep = true;
    }

    int m0 = blockIdx.y * 128, n0 = blockIdx.x * 128;
    if (m0 >= cnt) return;

    extern __shared__ float sm[];
    uint32_t sA = smem_u32(sm);
    uint32_t sB = sA + 2 * SOFF;

    int tid = threadIdx.x;
    int lane = tid & 31, w = tid >> 5;
    int wm = (w & 3) * 32, wn = (w >> 2) * 64;

    int lrow = tid >> 3;
    int lcol = (tid & 7) * 4;
    const float* gA[4]; const float* gB[4];
    uint32_t stA[4], stB[4];
#pragma unroll
    for (int rr = 0; rr < 4; rr++) {
        int mr = m0 + lrow + rr * 32;
        int grow;
        if (a_idx) grow = (mr < cnt) ? a_idx[mr] : 0;
        else       grow = mr;
        gA[rr] = A + (size_t)grow * args.lda + lcol;
        gB[rr] = B + (size_t)(n0 + lrow + rr * 32) * args.ldb + lcol;
        stA[rr] = sA + ((lrow + rr * 32) * SROW + lcol) * 4;
        stB[rr] = sB + ((lrow + rr * 32) * SROW + lcol) * 4;
    }

    uint32_t aAddr = sA + ((wm + (lane & 15)) * SROW + 4 * ((lane >> 4) & 1)) * 4;
    uint32_t bAddr = sB + ((wn + (lane & 7) + 8 * ((lane >> 4) & 1)) * SROW
                           + 4 * ((lane >> 3) & 1)) * 4;

    float acc[2][8][4];
#pragma unroll
    for (int i = 0; i < 2; i++)
#pragma unroll
        for (int j = 0; j < 8; j++)
#pragma unroll
            for (int q = 0; q < 4; q++) acc[i][j][q] = 0.f;

    int nk = args.K / BK;

    // prefetch stage 0
#pragma unroll
    for (int rr = 0; rr < 4; rr++) { cpa16(stA[rr], gA[rr]); cpa16(stB[rr], gB[rr]); }
    cpa_commit();

    for (int kt = 0; kt < nk; kt++) {
        cpa_wait0();
        __syncthreads();
        if (kt + 1 < nk) {
            int kb = (kt + 1) * BK;
            uint32_t off = ((kt + 1) & 1) * SOFF;
#pragma unroll
            for (int rr = 0; rr < 4; rr++) {
                cpa16(stA[rr] + off, gA[rr] + kb);
                cpa16(stB[rr] + off, gB[rr] + kb);
            }
        }
        cpa_commit();

        uint32_t soff = (kt & 1) * SOFF;
#pragma unroll
        for (int ks = 0; ks < 4; ks++) {
            uint32_t koff = soff + ks * 32;
            uint32_t a[2][4];
            ldsm4(a[0], aAddr + koff);
            ldsm4(a[1], aAddr + koff + 16 * SROW * 4);
            RND_FRAG(a[0]); RND_FRAG(a[1]);
            uint32_t b[4][4];
#pragma unroll
            for (int jp = 0; jp < 4; jp++) {
                ldsm4(b[jp], bAddr + koff + jp * (16 * SROW * 4));
                RND_FRAG(b[jp]);
            }
#pragma unroll
            for (int im = 0; im < 2; im++)
#pragma unroll
                for (int jn = 0; jn < 8; jn++)
                    mma8(acc[im][jn], a[im], b[jn >> 1][(jn & 1) * 2], b[jn >> 1][(jn & 1) * 2 + 1]);
        }
        __syncthreads();
    }

    int cg = 2 * (lane & 3);
#pragma unroll
    for (int im = 0; im < 2; im++) {
#pragma unroll
        for (int half = 0; half < 2; half++) {
            int m = m0 + wm + im * 16 + (lane >> 2) + half * 8;
            if (m >= cnt) continue;
            if (atomic_ep) {
                int tr = c_idx[m]; float wv = c_w[m];
                float* cp = C + (size_t)tr * args.ldc + n0 + wn + cg;
#pragma unroll
                for (int jn = 0; jn < 8; jn++) {
                    atomicAdd(cp + jn * 8,     wv * acc[im][jn][half * 2 + 0]);
                    atomicAdd(cp + jn * 8 + 1, wv * acc[im][jn][half * 2 + 1]);
                }
            } else if (args.resid) {
                const float* rp = args.resid + (size_t)m * args.ldc + n0 + wn + cg;
                float* cp = C + (size_t)m * args.ldc + n0 + wn + cg;
#pragma unroll
                for (int jn = 0; jn < 8; jn++) {
                    float2 r = *((const float2*)(rp + jn * 8));
                    float2 o;
                    o.x = acc[im][jn][half * 2 + 0] + r.x;
                    o.y = acc[im][jn][half * 2 + 1] + r.y;
                    *((float2*)(cp + jn * 8)) = o;
                }
            } else {
                float* cp = C + (size_t)m * args.ldc + n0 + wn + cg;
#pragma unroll
                for (int jn = 0; jn < 8; jn++) {
                    float2 o;
                    o.x = acc[im][jn][half * 2 + 0];
                    o.y = acc[im][jn][half * 2 + 1];
                    *((float2*)(cp + jn * 8)) = o;
                }
            }
        }
    }
}

// ==================== causal scores (3-stage pipelined, measured fast) ====================
__global__ void __launch_bounds__(256, 2)
attn_score_mma2(const float* __restrict__ Q, const float* __restrict__ Kt) {
    int bh = blockIdx.z, b = bh >> 4, h = bh & 15;
    int m0 = blockIdx.y * 128, n0 = blockIdx.x * 128;
    if (n0 > m0) return;

    const float* Qb = Q + (size_t)b * S_ * H_ + h * HD_;
    const float* Kb = Kt + (size_t)b * S_ * H_ + h * HD_;
    float* Sb = g_att + (size_t)bh * S_ * S_;

    extern __shared__ float sm[];
    uint32_t sA = smem_u32(sm);
    uint32_t sB = sA + 3 * SOFF;

    int tid = threadIdx.x;
    int lane = tid & 31, w = tid >> 5;
    int wm = (w & 3) * 32, wn = (w >> 2) * 64;

    int lrow = tid >> 3;
    int lcol = (tid & 7) * 4;
    const float* gA[4]; const float* gB[4];
    uint32_t stA[4], stB[4];
#pragma unroll
    for (int rr = 0; rr < 4; rr++) {
        gA[rr] = Qb + (size_t)(m0 + lrow + rr * 32) * H_ + lcol;
        gB[rr] = Kb + (size_t)(n0 + lrow + rr * 32) * H_ + lcol;
        stA[rr] = sA + ((lrow + rr * 32) * SROW + lcol) * 4;
        stB[rr] = sB + ((lrow + rr * 32) * SROW + lcol) * 4;
    }

    uint32_t aAddr = sA + ((wm + (lane & 15)) * SROW + 4 * ((lane >> 4) & 1)) * 4;
    uint32_t bAddr = sB + ((wn + (lane & 7) + 8 * ((lane >> 4) & 1)) * SROW
                           + 4 * ((lane >> 3) & 1)) * 4;

    float acc[2][8][4];
#pragma unroll
    for (int i = 0; i < 2; i++)
#pragma unroll
        for (int j = 0; j < 8; j++)
#pragma unroll
            for (int q = 0; q < 4; q++) acc[i][j][q] = 0.f;

    const int nk = HD_ / BK;   // 4

#pragma unroll
    for (int s = 0; s < 2; s++) {
        int kb = s * BK;
#pragma unroll
        for (int rr = 0; rr < 4; rr++) {
            cpa16(stA[rr] + s * SOFF, gA[rr] + kb);
            cpa16(stB[rr] + s * SOFF, gB[rr] + kb);
        }
        cpa_commit();
    }

    for (int kt = 0; kt < nk; kt++) {
        cpa_wait1();
        __syncthreads();
        if (kt + 2 < nk) {
            int kb = (kt + 2) * BK;
            uint32_t off = ((kt + 2) % 3) * SOFF;
#pragma unroll
            for (int rr = 0; rr < 4; rr++) {
                cpa16(stA[rr] + off, gA[rr] + kb);
                cpa16(stB[rr] + off, gB[rr] + kb);
            }
        }
        cpa_commit();

        uint32_t soff = (kt % 3) * SOFF;
#pragma unroll
        for (int ks = 0; ks < 4; ks++) {
            uint32_t koff = soff + ks * 32;
            uint32_t a[2][4];
            ldsm4(a[0], aAddr + koff);
            ldsm4(a[1], aAddr + koff + 16 * SROW * 4);
            RND_FRAG(a[0]); RND_FRAG(a[1]);
            uint32_t b2[4][4];
#pragma unroll
            for (int jp = 0; jp < 4; jp++) {
                ldsm4(b2[jp], bAddr + koff + jp * (16 * SROW * 4));
                RND_FRAG(b2[jp]);
            }
#pragma unroll
            for (int im = 0; im < 2; im++)
#pragma unroll
                for (int jn = 0; jn < 8; jn++)
                    mma8(acc[im][jn], a[im], b2[jn >> 1][(jn & 1) * 2], b2[jn >> 1][(jn & 1) * 2 + 1]);
        }
    }

    int cg = 2 * (lane & 3);
#pragma unroll
    for (int im = 0; im < 2; im++) {
#pragma unroll
        for (int half = 0; half < 2; half++) {
            int i = m0 + wm + im * 16 + (lane >> 2) + half * 8;
            float* cp = Sb + (size_t)i * S_ + n0 + wn + cg;
#pragma unroll
            for (int jn = 0; jn < 8; jn++) {
                int j = n0 + wn + cg + jn * 8;
                float2 o;
                o.x = (j     > i) ? -1e30f : acc[im][jn][half * 2 + 0] * ATT_SCALE;
                o.y = (j + 1 > i) ? -1e30f : acc[im][jn][half * 2 + 1] * ATT_SCALE;
                *((float2*)(cp + jn * 8)) = o;
            }
        }
    }
}

// ==================== adaptive row softmax ====================
__global__ void softmax_k() {
    int r = blockIdx.x & (S_ - 1);
    float* row = g_att + (size_t)blockIdx.x * S_;
    int len = r + 1;
    int tid = threadIdx.x;
    float v[8];
    float mx = -1e30f;
#pragma unroll
    for (int i = 0; i < 8; i++) {
        int j = tid + i * 256;
        v[i] = (j < len) ? row[j] : -1e30f;
        mx = fmaxf(mx, v[i]);
    }
    __shared__ float red[32];
    for (int off = 16; off; off >>= 1) mx = fmaxf(mx, __shfl_xor_sync(0xffffffffu, mx, off));
    if ((tid & 31) == 0) red[tid >> 5] = mx;
    __syncthreads();
    if (tid < 32) {
        float m2 = (tid < 8) ? red[tid] : -1e38f;
        for (int off = 16; off; off >>= 1) m2 = fmaxf(m2, __shfl_xor_sync(0xffffffffu, m2, off));
        if (tid == 0) red[0] = m2;
    }
    __syncthreads();
    mx = red[0];
    float s = 0.f;
#pragma unroll
    for (int i = 0; i < 8; i++) { v[i] = __expf(v[i] - mx); s += v[i]; }
    __syncthreads();
    for (int off = 16; off; off >>= 1) s += __shfl_xor_sync(0xffffffffu, s, off);
    if ((tid & 31) == 0) red[tid >> 5] = s;
    __syncthreads();
    if (tid < 32) {
        float s2 = (tid < 8) ? red[tid] : 0.f;
        for (int off = 16; off; off >>= 1) s2 += __shfl_xor_sync(0xffffffffu, s2, off);
        if (tid == 0) red[0] = s2;
    }
    __syncthreads();
    float inv = 1.f / red[0];
#pragma unroll
    for (int i = 0; i < 8; i++) {
        int j = tid + i * 256;
        if (j < len) row[j] = v[i] * inv;
    }
    int kmax = ((r >> 7) + 1) << 7;
    for (int j = len + tid; j < kmax; j += 256) row[j] = 0.f;
}

// ==================== P @ V (tf32 MMA, causal-truncated) ====================
__global__ void __launch_bounds__(256)
attn_pv_mma(const float* __restrict__ V) {
    int bh = blockIdx.y, b = bh >> 4, h = bh & 15;
    int m0 = blockIdx.x * 128;
    const float* Pb = g_att + (size_t)bh * S_ * S_;
    const float* Vb = V + (size_t)b * S_ * H_ + h * HD_;
    float* Ob = g_ao + (size_t)b * S_ * H_ + h * HD_;

    __shared__ uint32_t As[128][20];
    __shared__ uint32_t Bs[16][136];
    int tid = threadIdx.x;
    int lane = tid & 31, w = tid >> 5;
    int wm = (w & 3) * 32, wn = (w >> 2) * 64;
    int r1 = tid >> 2, c4 = (tid & 3) * 4;
    int kr = tid >> 5, nc4 = (tid & 31) * 4;

    const float* aP[2] = { Pb + (size_t)(m0 + r1) * S_ + c4,
                           Pb + (size_t)(m0 + r1 + 64) * S_ + c4 };

    float acc[2][8][4];
#pragma unroll
    for (int i = 0; i < 2; i++)
#pragma unroll
        for (int j = 0; j < 8; j++)
#pragma unroll
            for (int q = 0; q < 4; q++) acc[i][j][q] = 0.f;

    int kmax = m0 + 128;
    for (int kb = 0; kb < kmax; kb += 16) {
#pragma unroll
        for (int h2 = 0; h2 < 2; h2++) {
            float4 av = *(const float4*)(aP[h2] + kb);
            int rr = r1 + h2 * 64;
            As[rr][c4 + 0] = f2tf(av.x); As[rr][c4 + 1] = f2tf(av.y);
            As[rr][c4 + 2] = f2tf(av.z); As[rr][c4 + 3] = f2tf(av.w);
            float4 bv = *(const float4*)(Vb + (size_t)(kb + kr + h2 * 8) * H_ + nc4);
            int kk = kr + h2 * 8;
            Bs[kk][nc4 + 0] = f2tf(bv.x); Bs[kk][nc4 + 1] = f2tf(bv.y);
            Bs[kk][nc4 + 2] = f2tf(bv.z); Bs[kk][nc4 + 3] = f2tf(bv.w);
        }
        __syncthreads();
#pragma unroll
        for (int ks = 0; ks < 2; ks++) {
            int k0 = ks * 8 + (lane & 3);
            uint32_t af[2][4];
#pragma unroll
            for (int im = 0; im < 2; im++) {
                int mr = wm + im * 16 + (lane >> 2);
                af[im][0] = As[mr][k0];     af[im][1] = As[mr + 8][k0];
                af[im][2] = As[mr][k0 + 4]; af[im][3] = As[mr + 8][k0 + 4];
            }
#pragma unroll
            for (int jn = 0; jn < 8; jn++) {
                int nr = wn + jn * 8 + (lane >> 2);
                uint32_t b0 = Bs[k0][nr], b1 = Bs[k0 + 4][nr];
                mma8(acc[0][jn], af[0], b0, b1);
                mma8(acc[1][jn], af[1], b0, b1);
            }
        }
        __syncthreads();
    }

    int cg = 2 * (lane & 3);
#pragma unroll
    for (int im = 0; im < 2; im++) {
#pragma unroll
        for (int half = 0; half < 2; half++) {
            int m = m0 + wm + im * 16 + (lane >> 2) + half * 8;
            float* cp = Ob + (size_t)m * H_ + wn + cg;
#pragma unroll
            for (int jn = 0; jn < 8; jn++) {
                float2 o;
                o.x = acc[im][jn][half * 2 + 0];
                o.y = acc[im][jn][half * 2 + 1];
                *((float2*)(cp + jn * 8)) = o;
            }
        }
    }
}

// ==================== router ====================
__global__ void router_k(const float* __restrict__ xn2, const float* __restrict__ Wr) {
    int t = blockIdx.x * (blockDim.x >> 5) + (threadIdx.x >> 5);
    if (t >= T_) return;
    int lane = threadIdx.x & 31;
    const float* xr = xn2 + (size_t)t * H_;
    float s[NE_];
#pragma unroll
    for (int e = 0; e < NE_; e++) s[e] = 0.f;
    for (int j = lane; j < H_; j += 32) {
        float xv = xr[j];
#pragma unroll
        for (int e = 0; e < NE_; e++) s[e] += xv * Wr[e * H_ + j];
    }
#pragma unroll
    for (int e = 0; e < NE_; e++)
        for (int off = 16; off; off >>= 1) s[e] += __shfl_xor_sync(0xffffffffu, s[e], off);
    if (lane == 0) {
        int b0 = 0;
#pragma unroll
        for (int e = 1; e < NE_; e++) if (s[e] > s[b0]) b0 = e;
        int b1 = -1;
#pragma unroll
        for (int e = 0; e < NE_; e++) {
            if (e == b0) continue;
            if (b1 < 0 || s[e] > s[b1]) b1 = e;
        }
        float m = s[b0];
        float e0 = __expf(s[b0] - m), e1 = __expf(s[b1] - m);
        float inv = 1.f / (e0 + e1);
        int pos = atomicAdd(&g_cnt[b0], 1);
        g_tok[b0 * T_ + pos] = t; g_wt[b0 * T_ + pos] = e0 * inv;
        pos = atomicAdd(&g_cnt[b1], 1);
        g_tok[b1 * T_ + pos] = t; g_wt[b1 * T_ + pos] = e1 * inv;
    }
}

// ==================== host ====================
extern "C" void kernel_launch(void* const* d_in, const int* in_sizes, int n_in,
                              void* d_out, int out_size) {
    const float* x    = (const float*)d_in[0];
    const float* Wq   = (const float*)d_in[1];
    const float* Wk   = (const float*)d_in[2];
    const float* Wv   = (const float*)d_in[3];
    const float* Wo   = (const float*)d_in[4];
    const float* wln1 = (const float*)d_in[5];
    const float* wln2 = (const float*)d_in[6];
    const float* Wr   = (const float*)d_in[7];
    const float* Wg   = (const float*)d_in[8];
    const float* Wu   = (const float*)d_in[9];
    const float* Wd   = (const float*)d_in[10];
    float* out = (float*)d_out;

    float *p_xn, *p_q, *p_k, *p_v, *p_ao, *p_xn2, *p_hg, *p_hu, *p_wt;
    int *p_tok, *p_cnt;
    cudaGetSymbolAddress((void**)&p_xn,  g_xn);
    cudaGetSymbolAddress((void**)&p_q,   g_q);
    cudaGetSymbolAddress((void**)&p_k,   g_k);
    cudaGetSymbolAddress((void**)&p_v,   g_v);
    cudaGetSymbolAddress((void**)&p_ao,  g_ao);
    cudaGetSymbolAddress((void**)&p_xn2, g_xn2);
    cudaGetSymbolAddress((void**)&p_hg,  g_hg);
    cudaGetSymbolAddress((void**)&p_hu,  g_hu);
    cudaGetSymbolAddress((void**)&p_tok, g_tok);
    cudaGetSymbolAddress((void**)&p_wt,  g_wt);
    cudaGetSymbolAddress((void**)&p_cnt, g_cnt);

    static int smem_set = 0;
    if (!smem_set) {
        cudaFuncSetAttribute(mma_gemm2, cudaFuncAttributeMaxDynamicSharedMemorySize, SMEM_BYTES);
        cudaFuncSetAttribute(attn_score_mma2, cudaFuncAttributeMaxDynamicSharedMemorySize, SMEM_BYTES3);
        smem_set = 1;
    }

    zero_cnt_k<<<1, 32>>>();
    rmsnorm_k<<<T_, 256>>>(x, wln1, p_xn);

    // QKV fused launch
    {
        GArgs a = {};
        a.A = p_xn; a.B0 = Wq; a.B1 = Wk; a.B2 = Wv;
        a.C0 = p_q; a.C1 = p_k; a.C2 = p_v;
        a.M = T_; a.N = H_; a.K = H_; a.lda = H_; a.ldb = H_; a.ldc = H_;
        a.mode = 0;
        mma_gemm2<<<dim3(H_ / 128, T_ / 128, 3), 256, SMEM_BYTES>>>(a);
    }

    attn_score_mma2<<<dim3(S_ / 128, S_ / 128, B_ * NH_), 256, SMEM_BYTES3>>>(p_q, p_k);
    softmax_k<<<B_ * NH_ * S_, 256>>>();
    attn_pv_mma<<<dim3(S_ / 128, B_ * NH_), 256>>>(p_v);

    // Wo projection with fused residual: out = ao @ Wo^T + x
    {
        GArgs a = {};
        a.A = p_ao; a.B0 = Wo; a.C0 = out;
        a.resid = x;
        a.M = T_; a.N = H_; a.K = H_; a.lda = H_; a.ldb = H_; a.ldc = H_;
        a.mode = 0;
        mma_gemm2<<<dim3(H_ / 128, T_ / 128, 1), 256, SMEM_BYTES>>>(a);
    }

    rmsnorm_k<<<T_, 256>>>(out, wln2, p_xn2);
    router_k<<<T_ / 8, 256>>>(p_xn2, Wr);

    // MoE gate+up (gathered A)
    {
        GArgs a = {};
        a.A = p_xn2; a.B0 = Wg; a.B1 = Wu;
        a.C0 = p_hg; a.C1 = p_hu;
        a.M = T_; a.N = I_; a.K = H_; a.lda = H_; a.ldb = H_; a.ldc = I_;
        a.tok = p_tok; a.cntp = p_cnt;
        a.bStride = (size_t)I_ * H_; a.cStride = (size_t)T_ * I_;
        a.mode = 1;
        mma_gemm2<<<dim3(I_ / 128, T_ / 128, 2 * NE_), 256, SMEM_BYTES>>>(a);
    }

    swiglu_all_k<<<dim3(512, NE_), 256>>>(p_hg, p_hu);

    // MoE down: atomic scatter-add into out
    {
        GArgs a = {};
        a.A = p_hg; a.B0 = Wd; a.C0 = out;
        a.M = T_; a.N = H_; a.K = I_; a.lda = I_; a.ldb = I_; a.ldc = H_;
        a.tok = p_tok; a.wt = p_wt; a.cntp = p_cnt;
        a.aStride = (size_t)T_ * I_; a.bStride = (size_t)H_ * I_;
        a.mode = 2;
        mma_gemm2<<<dim3(H_ / 128, T_ / 128, NE_), 256, SMEM_BYTES>>>(a);
    }
}

// round 7
// speedup vs baseline: 1.0875x; 1.0875x over previous
#include <cuda_runtime.h>
#include <math.h>
#include <stdint.h>

#define B_   2
#define S_   2048
#define H_   2048
#define NH_  16
#define HD_  128
#define NE_  8
#define I_   4096
#define T_   (B_*S_)
#define EPS_ 1e-5f
#define ATT_SCALE 0.08838834764831845f

// -------------------- scratch --------------------
__device__ float g_xn [(size_t)T_*H_];   // ln1 out (rounded); later reused as ln2 EXACT out
__device__ float g_q  [(size_t)T_*H_];
__device__ float g_k  [(size_t)T_*H_];
__device__ float g_v  [(size_t)T_*H_];
__device__ float g_att[(size_t)B_*NH_*S_*S_];
__device__ float g_ao [(size_t)T_*H_];
__device__ float g_xn2[(size_t)T_*H_];   // ln2 out (rounded)
__device__ float g_hg [(size_t)NE_*T_*I_];
__device__ float g_hu [(size_t)NE_*T_*I_];
__device__ int   g_tok[NE_*T_];
__device__ float g_wt [NE_*T_];
__device__ int   g_cnt[NE_];

// -------------------- helpers --------------------
__device__ __forceinline__ uint32_t f2tf(float f) {
    uint32_t r; asm("cvt.rna.tf32.f32 %0, %1;" : "=r"(r) : "f"(f)); return r;
}
__device__ __forceinline__ float rtf(float f) {       // round-to-tf32, returned as fp32
    return __uint_as_float(f2tf(f));
}
__device__ __forceinline__ void mma8(float* c, const uint32_t* a, uint32_t b0, uint32_t b1) {
    asm volatile("mma.sync.aligned.m16n8k8.row.col.f32.tf32.tf32.f32 "
        "{%0,%1,%2,%3},{%4,%5,%6,%7},{%8,%9},{%0,%1,%2,%3};"
        : "+f"(c[0]), "+f"(c[1]), "+f"(c[2]), "+f"(c[3])
        : "r"(a[0]), "r"(a[1]), "r"(a[2]), "r"(a[3]), "r"(b0), "r"(b1));
}
__device__ __forceinline__ void ldsm4(uint32_t* r, uint32_t addr) {
    asm volatile("ldmatrix.sync.aligned.m8n8.x4.shared.b16 {%0,%1,%2,%3},[%4];"
        : "=r"(r[0]), "=r"(r[1]), "=r"(r[2]), "=r"(r[3]) : "r"(addr));
}
__device__ __forceinline__ void cpa16(uint32_t dst, const void* src) {
    asm volatile("cp.async.cg.shared.global [%0], [%1], 16;" :: "r"(dst), "l"(src));
}
__device__ __forceinline__ void cpa_commit() { asm volatile("cp.async.commit_group;"); }
__device__ __forceinline__ void cpa_wait0()  { asm volatile("cp.async.wait_group 0;" ::: "memory"); }
__device__ __forceinline__ void cpa_wait1()  { asm volatile("cp.async.wait_group 1;" ::: "memory"); }
__device__ __forceinline__ uint32_t smem_u32(const void* p) {
    uint32_t a; asm("{ .reg .u64 t; cvta.to.shared.u64 t, %1; cvt.u32.u64 %0, t; }"
                    : "=r"(a) : "l"(p));
    return a;
}

// -------------------- small kernels --------------------
__global__ void zero_cnt_k() { if (threadIdx.x < NE_) g_cnt[threadIdx.x] = 0; }

// rmsnorm: writes tf32-rounded output (GEMM A feed) and optionally the exact
// fp32 output (router feed — top-k decisions must see exact values).
__global__ void rmsnorm_k(const float* __restrict__ x, const float* __restrict__ w,
                          float* __restrict__ o_rnd, float* __restrict__ o_exact) {
    int t = blockIdx.x;
    const float* xr = x + (size_t)t * H_;
    float s = 0.f;
    for (int j = threadIdx.x; j < H_; j += blockDim.x) { float v = xr[j]; s += v * v; }
    __shared__ float red[32];
    for (int off = 16; off; off >>= 1) s += __shfl_xor_sync(0xffffffffu, s, off);
    if ((threadIdx.x & 31) == 0) red[threadIdx.x >> 5] = s;
    __syncthreads();
    if (threadIdx.x < 32) {
        float v = (threadIdx.x < (blockDim.x >> 5)) ? red[threadIdx.x] : 0.f;
        for (int off = 16; off; off >>= 1) v += __shfl_xor_sync(0xffffffffu, v, off);
        if (threadIdx.x == 0) red[0] = v;
    }
    __syncthreads();
    float inv = rsqrtf(red[0] / (float)H_ + EPS_);
    float* orow = o_rnd + (size_t)t * H_;
    if (o_exact) {
        float* erow = o_exact + (size_t)t * H_;
        for (int j = threadIdx.x; j < H_; j += blockDim.x) {
            float v = xr[j] * inv * w[j];
            erow[j] = v;
            orow[j] = rtf(v);
        }
    } else {
        for (int j = threadIdx.x; j < H_; j += blockDim.x)
            orow[j] = rtf(xr[j] * inv * w[j]);
    }
}

// swiglu with tf32-rounded output (feeds down-proj A)
__global__ void swiglu_all_k(float* __restrict__ hg, const float* __restrict__ hu) {
    int e = blockIdx.y;
    int cnt = g_cnt[e];
    float4* G = (float4*)(hg + (size_t)e * T_ * I_);
    const float4* U = (const float4*)(hu + (size_t)e * T_ * I_);
    size_t total = (size_t)cnt * (I_ / 4);
    size_t stride = (size_t)gridDim.x * blockDim.x;
    for (size_t i = (size_t)blockIdx.x * blockDim.x + threadIdx.x; i < total; i += stride) {
        float4 g = G[i], u = U[i];
        g.x = rtf(g.x / (1.f + __expf(-g.x)) * u.x);
        g.y = rtf(g.y / (1.f + __expf(-g.y)) * u.y);
        g.z = rtf(g.z / (1.f + __expf(-g.z)) * u.z);
        g.w = rtf(g.w / (1.f + __expf(-g.w)) * u.w);
        G[i] = g;
    }
}

// ==================== tf32 MMA GEMM (2-stage cp.async + ldmatrix) ====================
struct GArgs {
    const float* A;
    const float* B0; const float* B1; const float* B2;
    float* C0; float* C1; float* C2;
    const float* resid;
    int M, N, K, lda, ldb, ldc;
    const int* tok; const float* wt; const int* cntp;
    size_t aStride, bStride, cStride;
    int mode;
    int roundC;
};

#define BK 32
#define SROW 36
#define SOFF (128*SROW*4)
#define SMEM_BYTES (4*SOFF)            // 73728 B
#define SMEM_BYTES3 (6*SOFF)           // 110592 B (attn_score)

__global__ void __launch_bounds__(256, 2)
mma_gemm2(const GArgs args) {
    int z = blockIdx.z;
    const float* A = args.A;
    const float* B;
    float* C;
    const int* a_idx = nullptr; const int* c_idx = nullptr; const float* c_w = nullptr;
    int cnt = args.M;
    bool atomic_ep = false;

    if (args.mode == 0) {
        B = (z == 0) ? args.B0 : (z == 1 ? args.B1 : args.B2);
        C = (z == 0) ? args.C0 : (z == 1 ? args.C1 : args.C2);
    } else if (args.mode == 1) {
        int e = z >> 1;
        B = ((z & 1) ? args.B1 : args.B0) + (size_t)e * args.bStride;
        C = ((z & 1) ? args.C1 : args.C0) + (size_t)e * args.cStride;
        a_idx = args.tok + e * T_;
        cnt = args.cntp[e];
    } else {
        int e = z;
        A = args.A + (size_t)e * args.aStride;
        B = args.B0 + (size_t)e * args.bStride;
        C = args.C0;
        c_idx = args.tok + e * T_;
        c_w = args.wt + e * T_;
        cnt = args.cntp[e];
        atomic_ep = true;
    }

    int m0 = blockIdx.y * 128, n0 = blockIdx.x * 128;
    if (m0 >= cnt) return;

    extern __shared__ float sm[];
    uint32_t sA = smem_u32(sm);
    uint32_t sB = sA + 2 * SOFF;

    int tid = threadIdx.x;
    int lane = tid & 31, w = tid >> 5;
    int wm = (w & 3) * 32, wn = (w >> 2) * 64;

    int lrow = tid >> 3;
    int lcol = (tid & 7) * 4;
    const float* gA[4]; const float* gB[4];
    uint32_t stA[4], stB[4];
#pragma unroll
    for (int rr = 0; rr < 4; rr++) {
        int mr = m0 + lrow + rr * 32;
        int grow;
        if (a_idx) grow = (mr < cnt) ? a_idx[mr] : 0;
        else       grow = mr;
        gA[rr] = A + (size_t)grow * args.lda + lcol;
        gB[rr] = B + (size_t)(n0 + lrow + rr * 32) * args.ldb + lcol;
        stA[rr] = sA + ((lrow + rr * 32) * SROW + lcol) * 4;
        stB[rr] = sB + ((lrow + rr * 32) * SROW + lcol) * 4;
    }

    uint32_t aAddr = sA + ((wm + (lane & 15)) * SROW + 4 * ((lane >> 4) & 1)) * 4;
    uint32_t bAddr = sB + ((wn + (lane & 7) + 8 * ((lane >> 4) & 1)) * SROW
                           + 4 * ((lane >> 3) & 1)) * 4;

    float acc[2][8][4];
#pragma unroll
    for (int i = 0; i < 2; i++)
#pragma unroll
        for (int j = 0; j < 8; j++)
#pragma unroll
            for (int q = 0; q < 4; q++) acc[i][j][q] = 0.f;

    int nk = args.K / BK;

#pragma unroll
    for (int rr = 0; rr < 4; rr++) { cpa16(stA[rr], gA[rr]); cpa16(stB[rr], gB[rr]); }
    cpa_commit();

    for (int kt = 0; kt < nk; kt++) {
        cpa_wait0();
        __syncthreads();
        if (kt + 1 < nk) {
            int kb = (kt + 1) * BK;
            uint32_t off = ((kt + 1) & 1) * SOFF;
#pragma unroll
            for (int rr = 0; rr < 4; rr++) {
                cpa16(stA[rr] + off, gA[rr] + kb);
                cpa16(stB[rr] + off, gB[rr] + kb);
            }
        }
        cpa_commit();

        uint32_t soff = (kt & 1) * SOFF;
#pragma unroll
        for (int ks = 0; ks < 4; ks++) {
            uint32_t koff = soff + ks * 32;
            uint32_t a[2][4];
            ldsm4(a[0], aAddr + koff);
            ldsm4(a[1], aAddr + koff + 16 * SROW * 4);
            uint32_t b[4][4];
#pragma unroll
            for (int jp = 0; jp < 4; jp++)
                ldsm4(b[jp], bAddr + koff + jp * (16 * SROW * 4));
#pragma unroll
            for (int im = 0; im < 2; im++)
#pragma unroll
                for (int jn = 0; jn < 8; jn++)
                    mma8(acc[im][jn], a[im], b[jn >> 1][(jn & 1) * 2], b[jn >> 1][(jn & 1) * 2 + 1]);
        }
        __syncthreads();
    }

    int cg = 2 * (lane & 3);
#pragma unroll
    for (int im = 0; im < 2; im++) {
#pragma unroll
        for (int half = 0; half < 2; half++) {
            int m = m0 + wm + im * 16 + (lane >> 2) + half * 8;
            if (m >= cnt) continue;
            if (atomic_ep) {
                int tr = c_idx[m]; float wv = c_w[m];
                float* cp = C + (size_t)tr * args.ldc + n0 + wn + cg;
#pragma unroll
                for (int jn = 0; jn < 8; jn++) {
                    atomicAdd(cp + jn * 8,     wv * acc[im][jn][half * 2 + 0]);
                    atomicAdd(cp + jn * 8 + 1, wv * acc[im][jn][half * 2 + 1]);
                }
            } else if (args.resid) {
                const float* rp = args.resid + (size_t)m * args.ldc + n0 + wn + cg;
                float* cp = C + (size_t)m * args.ldc + n0 + wn + cg;
#pragma unroll
                for (int jn = 0; jn < 8; jn++) {
                    float2 r = *((const float2*)(rp + jn * 8));
                    float2 o;
                    o.x = acc[im][jn][half * 2 + 0] + r.x;
                    o.y = acc[im][jn][half * 2 + 1] + r.y;
                    *((float2*)(cp + jn * 8)) = o;
                }
            } else if (args.roundC) {
                float* cp = C + (size_t)m * args.ldc + n0 + wn + cg;
#pragma unroll
                for (int jn = 0; jn < 8; jn++) {
                    float2 o;
                    o.x = rtf(acc[im][jn][half * 2 + 0]);
                    o.y = rtf(acc[im][jn][half * 2 + 1]);
                    *((float2*)(cp + jn * 8)) = o;
                }
            } else {
                float* cp = C + (size_t)m * args.ldc + n0 + wn + cg;
#pragma unroll
                for (int jn = 0; jn < 8; jn++) {
                    float2 o;
                    o.x = acc[im][jn][half * 2 + 0];
                    o.y = acc[im][jn][half * 2 + 1];
                    *((float2*)(cp + jn * 8)) = o;
                }
            }
        }
    }
}

// ==================== causal scores (3-stage pipelined; q,k pre-rounded) ====================
__global__ void __launch_bounds__(256, 2)
attn_score_mma2(const float* __restrict__ Q, const float* __restrict__ Kt) {
    int bh = blockIdx.z, b = bh >> 4, h = bh & 15;
    int m0 = blockIdx.y * 128, n0 = blockIdx.x * 128;
    if (n0 > m0) return;

    const float* Qb = Q + (size_t)b * S_ * H_ + h * HD_;
    const float* Kb = Kt + (size_t)b * S_ * H_ + h * HD_;
    float* Sb = g_att + (size_t)bh * S_ * S_;

    extern __shared__ float sm[];
    uint32_t sA = smem_u32(sm);
    uint32_t sB = sA + 3 * SOFF;

    int tid = threadIdx.x;
    int lane = tid & 31, w = tid >> 5;
    int wm = (w & 3) * 32, wn = (w >> 2) * 64;

    int lrow = tid >> 3;
    int lcol = (tid & 7) * 4;
    const float* gA[4]; const float* gB[4];
    uint32_t stA[4], stB[4];
#pragma unroll
    for (int rr = 0; rr < 4; rr++) {
        gA[rr] = Qb + (size_t)(m0 + lrow + rr * 32) * H_ + lcol;
        gB[rr] = Kb + (size_t)(n0 + lrow + rr * 32) * H_ + lcol;
        stA[rr] = sA + ((lrow + rr * 32) * SROW + lcol) * 4;
        stB[rr] = sB + ((lrow + rr * 32) * SROW + lcol) * 4;
    }

    uint32_t aAddr = sA + ((wm + (lane & 15)) * SROW + 4 * ((lane >> 4) & 1)) * 4;
    uint32_t bAddr = sB + ((wn + (lane & 7) + 8 * ((lane >> 4) & 1)) * SROW
                           + 4 * ((lane >> 3) & 1)) * 4;

    float acc[2][8][4];
#pragma unroll
    for (int i = 0; i < 2; i++)
#pragma unroll
        for (int j = 0; j < 8; j++)
#pragma unroll
            for (int q = 0; q < 4; q++) acc[i][j][q] = 0.f;

    const int nk = HD_ / BK;

#pragma unroll
    for (int s = 0; s < 2; s++) {
        int kb = s * BK;
#pragma unroll
        for (int rr = 0; rr < 4; rr++) {
            cpa16(stA[rr] + s * SOFF, gA[rr] + kb);
            cpa16(stB[rr] + s * SOFF, gB[rr] + kb);
        }
        cpa_commit();
    }

    for (int kt = 0; kt < nk; kt++) {
        cpa_wait1();
        __syncthreads();
        if (kt + 2 < nk) {
            int kb = (kt + 2) * BK;
            uint32_t off = ((kt + 2) % 3) * SOFF;
#pragma unroll
            for (int rr = 0; rr < 4; rr++) {
                cpa16(stA[rr] + off, gA[rr] + kb);
                cpa16(stB[rr] + off, gB[rr] + kb);
            }
        }
        cpa_commit();

        uint32_t soff = (kt % 3) * SOFF;
#pragma unroll
        for (int ks = 0; ks < 4; ks++) {
            uint32_t koff = soff + ks * 32;
            uint32_t a[2][4];
            ldsm4(a[0], aAddr + koff);
            ldsm4(a[1], aAddr + koff + 16 * SROW * 4);
            uint32_t b2[4][4];
#pragma unroll
            for (int jp = 0; jp < 4; jp++)
                ldsm4(b2[jp], bAddr + koff + jp * (16 * SROW * 4));
#pragma unroll
            for (int im = 0; im < 2; im++)
#pragma unroll
                for (int jn = 0; jn < 8; jn++)
                    mma8(acc[im][jn], a[im], b2[jn >> 1][(jn & 1) * 2], b2[jn >> 1][(jn & 1) * 2 + 1]);
        }
    }

    int cg = 2 * (lane & 3);
#pragma unroll
    for (int im = 0; im < 2; im++) {
#pragma unroll
        for (int half = 0; half < 2; half++) {
            int i = m0 + wm + im * 16 + (lane >> 2) + half * 8;
            float* cp = Sb + (size_t)i * S_ + n0 + wn + cg;
#pragma unroll
            for (int jn = 0; jn < 8; jn++) {
                int j = n0 + wn + cg + jn * 8;
                float2 o;
                o.x = (j     > i) ? -1e30f : acc[im][jn][half * 2 + 0] * ATT_SCALE;
                o.y = (j + 1 > i) ? -1e30f : acc[im][jn][half * 2 + 1] * ATT_SCALE;
                *((float2*)(cp + jn * 8)) = o;
            }
        }
    }
}

// ==================== adaptive row softmax ====================
__global__ void softmax_k() {
    int r = blockIdx.x & (S_ - 1);
    float* row = g_att + (size_t)blockIdx.x * S_;
    int len = r + 1;
    int tid = threadIdx.x;
    float v[8];
    float mx = -1e30f;
#pragma unroll
    for (int i = 0; i < 8; i++) {
        int j = tid + i * 256;
        v[i] = (j < len) ? row[j] : -1e30f;
        mx = fmaxf(mx, v[i]);
    }
    __shared__ float red[32];
    for (int off = 16; off; off >>= 1) mx = fmaxf(mx, __shfl_xor_sync(0xffffffffu, mx, off));
    if ((tid & 31) == 0) red[tid >> 5] = mx;
    __syncthreads();
    if (tid < 32) {
        float m2 = (tid < 8) ? red[tid] : -1e38f;
        for (int off = 16; off; off >>= 1) m2 = fmaxf(m2, __shfl_xor_sync(0xffffffffu, m2, off));
        if (tid == 0) red[0] = m2;
    }
    __syncthreads();
    mx = red[0];
    float s = 0.f;
#pragma unroll
    for (int i = 0; i < 8; i++) { v[i] = __expf(v[i] - mx); s += v[i]; }
    __syncthreads();
    for (int off = 16; off; off >>= 1) s += __shfl_xor_sync(0xffffffffu, s, off);
    if ((tid & 31) == 0) red[tid >> 5] = s;
    __syncthreads();
    if (tid < 32) {
        float s2 = (tid < 8) ? red[tid] : 0.f;
        for (int off = 16; off; off >>= 1) s2 += __shfl_xor_sync(0xffffffffu, s2, off);
        if (tid == 0) red[0] = s2;
    }
    __syncthreads();
    float inv = 1.f / red[0];
#pragma unroll
    for (int i = 0; i < 8; i++) {
        int j = tid + i * 256;
        if (j < len) row[j] = v[i] * inv;
    }
    int kmax = ((r >> 7) + 1) << 7;
    for (int j = len + tid; j < kmax; j += 256) row[j] = 0.f;
}

// ==================== P @ V (tf32 MMA, causal-truncated; rna on fill) ====================
__global__ void __launch_bounds__(256)
attn_pv_mma(const float* __restrict__ V) {
    int bh = blockIdx.y, b = bh >> 4, h = bh & 15;
    int m0 = blockIdx.x * 128;
    const float* Pb = g_att + (size_t)bh * S_ * S_;
    const float* Vb = V + (size_t)b * S_ * H_ + h * HD_;
    float* Ob = g_ao + (size_t)b * S_ * H_ + h * HD_;

    __shared__ uint32_t As[128][20];
    __shared__ uint32_t Bs[16][136];
    int tid = threadIdx.x;
    int lane = tid & 31, w = tid >> 5;
    int wm = (w & 3) * 32, wn = (w >> 2) * 64;
    int r1 = tid >> 2, c4 = (tid & 3) * 4;
    int kr = tid >> 5, nc4 = (tid & 31) * 4;

    const float* aP[2] = { Pb + (size_t)(m0 + r1) * S_ + c4,
                           Pb + (size_t)(m0 + r1 + 64) * S_ + c4 };

    float acc[2][8][4];
#pragma unroll
    for (int i = 0; i < 2; i++)
#pragma unroll
        for (int j = 0; j < 8; j++)
#pragma unroll
            for (int q = 0; q < 4; q++) acc[i][j][q] = 0.f;

    int kmax = m0 + 128;
    for (int kb = 0; kb < kmax; kb += 16) {
#pragma unroll
        for (int h2 = 0; h2 < 2; h2++) {
            float4 av = *(const float4*)(aP[h2] + kb);
            int rr = r1 + h2 * 64;
            As[rr][c4 + 0] = f2tf(av.x); As[rr][c4 + 1] = f2tf(av.y);
            As[rr][c4 + 2] = f2tf(av.z); As[rr][c4 + 3] = f2tf(av.w);
            float4 bv = *(const float4*)(Vb + (size_t)(kb + kr + h2 * 8) * H_ + nc4);
            int kk = kr + h2 * 8;
            Bs[kk][nc4 + 0] = f2tf(bv.x); Bs[kk][nc4 + 1] = f2tf(bv.y);
            Bs[kk][nc4 + 2] = f2tf(bv.z); Bs[kk][nc4 + 3] = f2tf(bv.w);
        }
        __syncthreads();
#pragma unroll
        for (int ks = 0; ks < 2; ks++) {
            int k0 = ks * 8 + (lane & 3);
            uint32_t af[2][4];
#pragma unroll
            for (int im = 0; im < 2; im++) {
                int mr = wm + im * 16 + (lane >> 2);
                af[im][0] = As[mr][k0];     af[im][1] = As[mr + 8][k0];
                af[im][2] = As[mr][k0 + 4]; af[im][3] = As[mr + 8][k0 + 4];
            }
#pragma unroll
            for (int jn = 0; jn < 8; jn++) {
                int nr = wn + jn * 8 + (lane >> 2);
                uint32_t b0 = Bs[k0][nr], b1 = Bs[k0 + 4][nr];
                mma8(acc[0][jn], af[0], b0, b1);
                mma8(acc[1][jn], af[1], b0, b1);
            }
        }
        __syncthreads();
    }

    int cg = 2 * (lane & 3);
#pragma unroll
    for (int im = 0; im < 2; im++) {
#pragma unroll
        for (int half = 0; half < 2; half++) {
            int m = m0 + wm + im * 16 + (lane >> 2) + half * 8;
            float* cp = Ob + (size_t)m * H_ + wn + cg;
#pragma unroll
            for (int jn = 0; jn < 8; jn++) {
                float2 o;
                o.x = rtf(acc[im][jn][half * 2 + 0]);   // ao feeds Wo GEMM A
                o.y = rtf(acc[im][jn][half * 2 + 1]);
                *((float2*)(cp + jn * 8)) = o;
            }
        }
    }
}

// ==================== router (EXACT fp32 input — top-k is discrete) ====================
__global__ void router_k(const float* __restrict__ xn2e, const float* __restrict__ Wr) {
    int t = blockIdx.x * (blockDim.x >> 5) + (threadIdx.x >> 5);
    if (t >= T_) return;
    int lane = threadIdx.x & 31;
    const float* xr = xn2e + (size_t)t * H_;
    float s[NE_];
#pragma unroll
    for (int e = 0; e < NE_; e++) s[e] = 0.f;
    for (int j = lane; j < H_; j += 32) {
        float xv = xr[j];
#pragma unroll
        for (int e = 0; e < NE_; e++) s[e] += xv * Wr[e * H_ + j];
    }
#pragma unroll
    for (int e = 0; e < NE_; e++)
        for (int off = 16; off; off >>= 1) s[e] += __shfl_xor_sync(0xffffffffu, s[e], off);
    if (lane == 0) {
        int b0 = 0;
#pragma unroll
        for (int e = 1; e < NE_; e++) if (s[e] > s[b0]) b0 = e;
        int b1 = -1;
#pragma unroll
        for (int e = 0; e < NE_; e++) {
            if (e == b0) continue;
            if (b1 < 0 || s[e] > s[b1]) b1 = e;
        }
        float m = s[b0];
        float e0 = __expf(s[b0] - m), e1 = __expf(s[b1] - m);
        float inv = 1.f / (e0 + e1);
        int pos = atomicAdd(&g_cnt[b0], 1);
        g_tok[b0 * T_ + pos] = t; g_wt[b0 * T_ + pos] = e0 * inv;
        pos = atomicAdd(&g_cnt[b1], 1);
        g_tok[b1 * T_ + pos] = t; g_wt[b1 * T_ + pos] = e1 * inv;
    }
}

// ==================== host ====================
extern "C" void kernel_launch(void* const* d_in, const int* in_sizes, int n_in,
                              void* d_out, int out_size) {
    const float* x    = (const float*)d_in[0];
    const float* Wq   = (const float*)d_in[1];
    const float* Wk   = (const float*)d_in[2];
    const float* Wv   = (const float*)d_in[3];
    const float* Wo   = (const float*)d_in[4];
    const float* wln1 = (const float*)d_in[5];
    const float* wln2 = (const float*)d_in[6];
    const float* Wr   = (const float*)d_in[7];
    const float* Wg   = (const float*)d_in[8];
    const float* Wu   = (const float*)d_in[9];
    const float* Wd   = (const float*)d_in[10];
    float* out = (float*)d_out;

    float *p_xn, *p_q, *p_k, *p_v, *p_ao, *p_xn2, *p_hg, *p_hu, *p_wt;
    int *p_tok, *p_cnt;
    cudaGetSymbolAddress((void**)&p_xn,  g_xn);
    cudaGetSymbolAddress((void**)&p_q,   g_q);
    cudaGetSymbolAddress((void**)&p_k,   g_k);
    cudaGetSymbolAddress((void**)&p_v,   g_v);
    cudaGetSymbolAddress((void**)&p_ao,  g_ao);
    cudaGetSymbolAddress((void**)&p_xn2, g_xn2);
    cudaGetSymbolAddress((void**)&p_hg,  g_hg);
    cudaGetSymbolAddress((void**)&p_hu,  g_hu);
    cudaGetSymbolAddress((void**)&p_tok, g_tok);
    cudaGetSymbolAddress((void**)&p_wt,  g_wt);
    cudaGetSymbolAddress((void**)&p_cnt, g_cnt);

    static int smem_set = 0;
    if (!smem_set) {
        cudaFuncSetAttribute(mma_gemm2, cudaFuncAttributeMaxDynamicSharedMemorySize, SMEM_BYTES);
        cudaFuncSetAttribute(attn_score_mma2, cudaFuncAttributeMaxDynamicSharedMemorySize, SMEM_BYTES3);
        smem_set = 1;
    }

    zero_cnt_k<<<1, 32>>>();
    rmsnorm_k<<<T_, 256>>>(x, wln1, p_xn, nullptr);   // rounded only (QKV A feed)

    // QKV fused launch; outputs rounded to tf32 (feed score/PV MMAs)
    {
        GArgs a = {};
        a.A = p_xn; a.B0 = Wq; a.B1 = Wk; a.B2 = Wv;
        a.C0 = p_q; a.C1 = p_k; a.C2 = p_v;
        a.M = T_; a.N = H_; a.K = H_; a.lda = H_; a.ldb = H_; a.ldc = H_;
        a.mode = 0; a.roundC = 1;
        mma_gemm2<<<dim3(H_ / 128, T_ / 128, 3), 256, SMEM_BYTES>>>(a);
    }

    attn_score_mma2<<<dim3(S_ / 128, S_ / 128, B_ * NH_), 256, SMEM_BYTES3>>>(p_q, p_k);
    softmax_k<<<B_ * NH_ * S_, 256>>>();
    attn_pv_mma<<<dim3(S_ / 128, B_ * NH_), 256>>>(p_v);

    // Wo projection with fused residual: out = ao @ Wo^T + x
    {
        GArgs a = {};
        a.A = p_ao; a.B0 = Wo; a.C0 = out;
        a.resid = x;
        a.M = T_; a.N = H_; a.K = H_; a.lda = H_; a.ldb = H_; a.ldc = H_;
        a.mode = 0;
        mma_gemm2<<<dim3(H_ / 128, T_ / 128, 1), 256, SMEM_BYTES>>>(a);
    }

    // ln2: rounded -> g_xn2 (GEMM A), exact -> g_xn (router; buffer reused)
    rmsnorm_k<<<T_, 256>>>(out, wln2, p_xn2, p_xn);
    router_k<<<T_ / 8, 256>>>(p_xn, Wr);

    // MoE gate+up (gathered A, rounded activations)
    {
        GArgs a = {};
        a.A = p_xn2; a.B0 = Wg; a.B1 = Wu;
        a.C0 = p_hg; a.C1 = p_hu;
        a.M = T_; a.N = I_; a.K = H_; a.lda = H_; a.ldb = H_; a.ldc = I_;
        a.tok = p_tok; a.cntp = p_cnt;
        a.bStride = (size_t)I_ * H_; a.cStride = (size_t)T_ * I_;
        a.mode = 1;
        mma_gemm2<<<dim3(I_ / 128, T_ / 128, 2 * NE_), 256, SMEM_BYTES>>>(a);
    }

    swiglu_all_k<<<dim3(512, NE_), 256>>>(p_hg, p_hu);

    // MoE down: atomic scatter-add into out
    {
        GArgs a = {};
        a.A = p_hg; a.B0 = Wd; a.C0 = out;
        a.M = T_; a.N = H_; a.K = I_; a.lda = I_; a.ldb = I_; a.ldc = H_;
        a.tok = p_tok; a.wt = p_wt; a.cntp = p_cnt;
        a.aStride = (size_t)T_ * I_; a.bStride = (size_t)H_ * I_;
        a.mode = 2;
        mma_gemm2<<<dim3(H_ / 128, T_ / 128, NE_), 256, SMEM_BYTES>>>(a);
    }
}

// round 9
// speedup vs baseline: 1.5084x; 1.3871x over previous
#include <cuda_runtime.h>
#include <cuda_fp16.h>
#include <math.h>
#include <stdint.h>

#define B_   2
#define S_   2048
#define H_   2048
#define NH_  16
#define HD_  128
#define NE_  8
#define I_   4096
#define T_   (B_*S_)
#define EPS_ 1e-5f
#define ATT_SCALE 0.08838834764831845f

// -------------------- scratch --------------------
__device__ float  g_q  [(size_t)T_*H_];   // q (fp32, tf32-rounded); later reused: router exact in
__device__ float  g_k  [(size_t)T_*H_];
__device__ float  g_v  [(size_t)T_*H_];
__device__ float  g_att[(size_t)B_*NH_*S_*S_];
__device__ float  g_hg [(size_t)NE_*T_*I_];
__device__ float  g_hu [(size_t)NE_*T_*I_];
__device__ __half g_xn16 [(size_t)T_*H_];     // ln1 out (fp16)
__device__ __half g_ao16 [(size_t)T_*H_];     // attn out (fp16, Wo A)
__device__ __half g_xn216[(size_t)T_*H_];     // ln2 out (fp16)
__device__ __half g_hg16 [(size_t)NE_*T_*I_]; // swiglu out (fp16, down A)
// fp16 weights (converted per launch)
#define OFF_WQ ((size_t)0)
#define OFF_WK ((size_t)H_*H_)
#define OFF_WV ((size_t)2*H_*H_)
#define OFF_WO ((size_t)3*H_*H_)
#define OFF_WG ((size_t)4*H_*H_)
#define OFF_WU (OFF_WG + (size_t)NE_*I_*H_)
#define OFF_WD (OFF_WU + (size_t)NE_*I_*H_)
#define W16_TOTAL (OFF_WD + (size_t)NE_*H_*I_)
__device__ __half g_w16[W16_TOTAL];
__device__ int   g_tok[NE_*T_];
__device__ float g_wt [NE_*T_];
__device__ int   g_cnt[NE_];

// -------------------- helpers --------------------
__device__ __forceinline__ uint32_t f2tf(float f) {
    uint32_t r; asm("cvt.rna.tf32.f32 %0, %1;" : "=r"(r) : "f"(f)); return r;
}
__device__ __forceinline__ float rtf(float f) { return __uint_as_float(f2tf(f)); }
__device__ __forceinline__ void mma8(float* c, const uint32_t* a, uint32_t b0, uint32_t b1) {
    asm volatile("mma.sync.aligned.m16n8k8.row.col.f32.tf32.tf32.f32 "
        "{%0,%1,%2,%3},{%4,%5,%6,%7},{%8,%9},{%0,%1,%2,%3};"
        : "+f"(c[0]), "+f"(c[1]), "+f"(c[2]), "+f"(c[3])
        : "r"(a[0]), "r"(a[1]), "r"(a[2]), "r"(a[3]), "r"(b0), "r"(b1));
}
__device__ __forceinline__ void mma16h(float* c, const uint32_t* a, uint32_t b0, uint32_t b1) {
    asm volatile("mma.sync.aligned.m16n8k16.row.col.f32.f16.f16.f32 "
        "{%0,%1,%2,%3},{%4,%5,%6,%7},{%8,%9},{%0,%1,%2,%3};"
        : "+f"(c[0]), "+f"(c[1]), "+f"(c[2]), "+f"(c[3])
        : "r"(a[0]), "r"(a[1]), "r"(a[2]), "r"(a[3]), "r"(b0), "r"(b1));
}
__device__ __forceinline__ void ldsm4(uint32_t* r, uint32_t addr) {
    asm volatile("ldmatrix.sync.aligned.m8n8.x4.shared.b16 {%0,%1,%2,%3},[%4];"
        : "=r"(r[0]), "=r"(r[1]), "=r"(r[2]), "=r"(r[3]) : "r"(addr));
}
__device__ __forceinline__ void cpa16(uint32_t dst, const void* src) {
    asm volatile("cp.async.cg.shared.global [%0], [%1], 16;" :: "r"(dst), "l"(src));
}
__device__ __forceinline__ void cpa_commit() { asm volatile("cp.async.commit_group;"); }
__device__ __forceinline__ void cpa_wait1()  { asm volatile("cp.async.wait_group 1;" ::: "memory"); }
__device__ __forceinline__ uint32_t smem_u32(const void* p) {
    uint32_t a; asm("{ .reg .u64 t; cvta.to.shared.u64 t, %1; cvt.u32.u64 %0, t; }"
                    : "=r"(a) : "l"(p));
    return a;
}

// -------------------- small kernels --------------------
__global__ void zero_cnt_k() { if (threadIdx.x < NE_) g_cnt[threadIdx.x] = 0; }

// fp32 -> fp16 weight conversion (grid-stride, n multiple of 4)
__global__ void cvt16_k(const float* __restrict__ s, __half* __restrict__ d, size_t n4) {
    size_t stride = (size_t)gridDim.x * blockDim.x;
    const float4* S = (const float4*)s;
    __half2* D = (__half2*)d;
    for (size_t i = (size_t)blockIdx.x * blockDim.x + threadIdx.x; i < n4; i += stride) {
        float4 v = S[i];
        D[2 * i]     = __floats2half2_rn(v.x, v.y);
        D[2 * i + 1] = __floats2half2_rn(v.z, v.w);
    }
}

// rmsnorm: fp16 output (GEMM A feed) + optional exact fp32 (router feed)
__global__ void rmsnorm_k(const float* __restrict__ x, const float* __restrict__ w,
                          __half* __restrict__ o16, float* __restrict__ o_exact) {
    int t = blockIdx.x;
    const float* xr = x + (size_t)t * H_;
    float s = 0.f;
    for (int j = threadIdx.x; j < H_; j += blockDim.x) { float v = xr[j]; s += v * v; }
    __shared__ float red[32];
    for (int off = 16; off; off >>= 1) s += __shfl_xor_sync(0xffffffffu, s, off);
    if ((threadIdx.x & 31) == 0) red[threadIdx.x >> 5] = s;
    __syncthreads();
    if (threadIdx.x < 32) {
        float v = (threadIdx.x < (blockDim.x >> 5)) ? red[threadIdx.x] : 0.f;
        for (int off = 16; off; off >>= 1) v += __shfl_xor_sync(0xffffffffu, v, off);
        if (threadIdx.x == 0) red[0] = v;
    }
    __syncthreads();
    float inv = rsqrtf(red[0] / (float)H_ + EPS_);
    __half* orow = o16 + (size_t)t * H_;
    if (o_exact) {
        float* erow = o_exact + (size_t)t * H_;
        for (int j = threadIdx.x; j < H_; j += blockDim.x) {
            float v = xr[j] * inv * w[j];
            erow[j] = v;
            orow[j] = __float2half_rn(v);
        }
    } else {
        for (int j = threadIdx.x; j < H_; j += blockDim.x)
            orow[j] = __float2half_rn(xr[j] * inv * w[j]);
    }
}

// swiglu: fp32 in, fp16 out (down-proj A)
__global__ void swiglu_all_k(const float* __restrict__ hg, const float* __restrict__ hu,
                             __half* __restrict__ ho) {
    int e = blockIdx.y;
    int cnt = g_cnt[e];
    const float4* G = (const float4*)(hg + (size_t)e * T_ * I_);
    const float4* U = (const float4*)(hu + (size_t)e * T_ * I_);
    __half2* O = (__half2*)(ho + (size_t)e * T_ * I_);
    size_t total = (size_t)cnt * (I_ / 4);
    size_t stride = (size_t)gridDim.x * blockDim.x;
    for (size_t i = (size_t)blockIdx.x * blockDim.x + threadIdx.x; i < total; i += stride) {
        float4 g = G[i], u = U[i];
        float a = g.x / (1.f + __expf(-g.x)) * u.x;
        float b = g.y / (1.f + __expf(-g.y)) * u.y;
        float c = g.z / (1.f + __expf(-g.z)) * u.z;
        float d = g.w / (1.f + __expf(-g.w)) * u.w;
        O[2 * i]     = __floats2half2_rn(a, b);
        O[2 * i + 1] = __floats2half2_rn(c, d);
    }
}

// ==================== fp16 MMA GEMM (3-stage cp.async + ldmatrix) ====================
// C[M,N] = A[M,K] * B[N,K]^T.  A, B fp16; C fp32.
// Mode 0: z selects (B,C) among {B0/C0,B1/C1,B2/C2}; optional resid / roundC.
// Mode 1: z = expert*2+{gate,up}; A rows gathered via token list; dense store.
// Mode 2: z = expert; dense per-expert A; atomic scatter-add epilogue.
struct GArgs {
    const __half* A;
    const __half* B0; const __half* B1; const __half* B2;
    float* C0; float* C1; float* C2;
    const float* resid;
    int M, N, K, lda, ldb, ldc;
    const int* tok; const float* wt; const int* cntp;
    size_t aStride, bStride, cStride;
    int mode;
    int roundC;
};

#define HROWB 80                      // bytes per smem row (64 data + 16 pad)
#define H_STG 3
#define H_STAGE (128*HROWB)           // 10240 B per matrix-stage
#define H_SMEM (2*H_STG*H_STAGE)      // 61440 B

__global__ void __launch_bounds__(256, 2)
hgemm(const GArgs args) {
    int z = blockIdx.z;
    const __half* A = args.A;
    const __half* B;
    float* C;
    const int* a_idx = nullptr; const int* c_idx = nullptr; const float* c_w = nullptr;
    int cnt = args.M;
    bool atomic_ep = false;

    if (args.mode == 0) {
        B = (z == 0) ? args.B0 : (z == 1 ? args.B1 : args.B2);
        C = (z == 0) ? args.C0 : (z == 1 ? args.C1 : args.C2);
    } else if (args.mode == 1) {
        int e = z >> 1;
        B = ((z & 1) ? args.B1 : args.B0) + (size_t)e * args.bStride;
        C = ((z & 1) ? args.C1 : args.C0) + (size_t)e * args.cStride;
        a_idx = args.tok + e * T_;
        cnt = args.cntp[e];
    } else {
        int e = z;
        A = args.A + (size_t)e * args.aStride;
        B = args.B0 + (size_t)e * args.bStride;
        C = args.C0;
        c_idx = args.tok + e * T_;
        c_w = args.wt + e * T_;
        cnt = args.cntp[e];
        atomic_ep = true;
    }

    int m0 = blockIdx.y * 128, n0 = blockIdx.x * 128;
    if (m0 >= cnt) return;

    extern __shared__ char smem[];
    uint32_t sA = smem_u32(smem);
    uint32_t sB = sA + H_STG * H_STAGE;

    int tid = threadIdx.x;
    int lane = tid & 31, w = tid >> 5;
    int wm = (w & 3) * 32, wn = (w >> 2) * 64;

    // loader: 2 passes of 64 rows; each thread one 16B chunk per row
    int lrow = tid >> 2;           // 0..63
    int lch  = tid & 3;            // 16B chunk (8 halves)
    const __half* gA[2]; const __half* gB[2];
    uint32_t stA[2], stB[2];
#pragma unroll
    for (int rr = 0; rr < 2; rr++) {
        int r = lrow + rr * 64;
        int mr = m0 + r;
        int grow = a_idx ? ((mr < cnt) ? a_idx[mr] : 0) : mr;
        gA[rr] = A + (size_t)grow * args.lda + lch * 8;
        gB[rr] = B + (size_t)(n0 + r) * args.ldb + lch * 8;
        stA[rr] = sA + r * HROWB + lch * 16;
        stB[rr] = sB + r * HROWB + lch * 16;
    }

    // ldmatrix addresses
    uint32_t aAddr = sA + (wm + (lane & 15)) * HROWB + ((lane >> 4) & 1) * 16;
    uint32_t bAddr = sB + (wn + (lane & 7) + 8 * ((lane >> 4) & 1)) * HROWB
                        + ((lane >> 3) & 1) * 16;

    float acc[2][8][4];
#pragma unroll
    for (int i = 0; i < 2; i++)
#pragma unroll
        for (int j = 0; j < 8; j++)
#pragma unroll
            for (int q = 0; q < 4; q++) acc[i][j][q] = 0.f;

    int nk = args.K / 32;

    // prologue: stages 0,1
#pragma unroll
    for (int s = 0; s < 2; s++) {
#pragma unroll
        for (int rr = 0; rr < 2; rr++) {
            cpa16(stA[rr] + s * H_STAGE, gA[rr] + s * 32);
            cpa16(stB[rr] + s * H_STAGE, gB[rr] + s * 32);
        }
        cpa_commit();
    }

    for (int kt = 0; kt < nk; kt++) {
        cpa_wait1();
        __syncthreads();
        if (kt + 2 < nk) {
            int kb = (kt + 2) * 32;
            uint32_t off = ((kt + 2) % H_STG) * H_STAGE;
#pragma unroll
            for (int rr = 0; rr < 2; rr++) {
                cpa16(stA[rr] + off, gA[rr] + kb);
                cpa16(stB[rr] + off, gB[rr] + kb);
            }
        }
        cpa_commit();

        uint32_t soff = (kt % H_STG) * H_STAGE;
#pragma unroll
        for (int ks = 0; ks < 2; ks++) {
            uint32_t koff = soff + ks * 32;
            uint32_t a[2][4];
            ldsm4(a[0], aAddr + koff);
            ldsm4(a[1], aAddr + koff + 16 * HROWB);
            uint32_t b[4][4];
#pragma unroll
            for (int jp = 0; jp < 4; jp++)
                ldsm4(b[jp], bAddr + koff + jp * (16 * HROWB));
#pragma unroll
            for (int im = 0; im < 2; im++)
#pragma unroll
                for (int jn = 0; jn < 8; jn++)
                    mma16h(acc[im][jn], a[im], b[jn >> 1][(jn & 1) * 2], b[jn >> 1][(jn & 1) * 2 + 1]);
        }
        __syncthreads();
    }

    int cg = 2 * (lane & 3);
#pragma unroll
    for (int im = 0; im < 2; im++) {
#pragma unroll
        for (int half = 0; half < 2; half++) {
            int m = m0 + wm + im * 16 + (lane >> 2) + half * 8;
            if (m >= cnt) continue;
            if (atomic_ep) {
                int tr = c_idx[m]; float wv = c_w[m];
                float* cp = C + (size_t)tr * args.ldc + n0 + wn + cg;
#pragma unroll
                for (int jn = 0; jn < 8; jn++) {
                    atomicAdd(cp + jn * 8,     wv * acc[im][jn][half * 2 + 0]);
                    atomicAdd(cp + jn * 8 + 1, wv * acc[im][jn][half * 2 + 1]);
                }
            } else if (args.resid) {
                const float* rp = args.resid + (size_t)m * args.ldc + n0 + wn + cg;
                float* cp = C + (size_t)m * args.ldc + n0 + wn + cg;
#pragma unroll
                for (int jn = 0; jn < 8; jn++) {
                    float2 r = *((const float2*)(rp + jn * 8));
                    float2 o;
                    o.x = acc[im][jn][half * 2 + 0] + r.x;
                    o.y = acc[im][jn][half * 2 + 1] + r.y;
                    *((float2*)(cp + jn * 8)) = o;
                }
            } else if (args.roundC) {
                float* cp = C + (size_t)m * args.ldc + n0 + wn + cg;
#pragma unroll
                for (int jn = 0; jn < 8; jn++) {
                    float2 o;
                    o.x = rtf(acc[im][jn][half * 2 + 0]);
                    o.y = rtf(acc[im][jn][half * 2 + 1]);
                    *((float2*)(cp + jn * 8)) = o;
                }
            } else {
                float* cp = C + (size_t)m * args.ldc + n0 + wn + cg;
#pragma unroll
                for (int jn = 0; jn < 8; jn++) {
                    float2 o;
                    o.x = acc[im][jn][half * 2 + 0];
                    o.y = acc[im][jn][half * 2 + 1];
                    *((float2*)(cp + jn * 8)) = o;
                }
            }
        }
    }
}

// ==================== causal scores (tf32, 3-stage pipelined ldsm) ====================
#define BK 32
#define SROW 36
#define SOFF (128*SROW*4)
#define SMEM_BYTES3 (6*SOFF)

__global__ void __launch_bounds__(256, 2)
attn_score_mma2(const float* __restrict__ Q, const float* __restrict__ Kt) {
    int bh = blockIdx.z, b = bh >> 4, h = bh & 15;
    int m0 = blockIdx.y * 128, n0 = blockIdx.x * 128;
    if (n0 > m0) return;

    const float* Qb = Q + (size_t)b * S_ * H_ + h * HD_;
    const float* Kb = Kt + (size_t)b * S_ * H_ + h * HD_;
    float* Sb = g_att + (size_t)bh * S_ * S_;

    extern __shared__ float sm[];
    uint32_t sA = smem_u32(sm);
    uint32_t sB = sA + 3 * SOFF;

    int tid = threadIdx.x;
    int lane = tid & 31, w = tid >> 5;
    int wm = (w & 3) * 32, wn = (w >> 2) * 64;

    int lrow = tid >> 3;
    int lcol = (tid & 7) * 4;
    const float* gA[4]; const float* gB[4];
    uint32_t stA[4], stB[4];
#pragma unroll
    for (int rr = 0; rr < 4; rr++) {
        gA[rr] = Qb + (size_t)(m0 + lrow + rr * 32) * H_ + lcol;
        gB[rr] = Kb + (size_t)(n0 + lrow + rr * 32) * H_ + lcol;
        stA[rr] = sA + ((lrow + rr * 32) * SROW + lcol) * 4;
        stB[rr] = sB + ((lrow + rr * 32) * SROW + lcol) * 4;
    }

    uint32_t aAddr = sA + ((wm + (lane & 15)) * SROW + 4 * ((lane >> 4) & 1)) * 4;
    uint32_t bAddr = sB + ((wn + (lane & 7) + 8 * ((lane >> 4) & 1)) * SROW
                           + 4 * ((lane >> 3) & 1)) * 4;

    float acc[2][8][4];
#pragma unroll
    for (int i = 0; i < 2; i++)
#pragma unroll
        for (int j = 0; j < 8; j++)
#pragma unroll
            for (int q = 0; q < 4; q++) acc[i][j][q] = 0.f;

    const int nk = HD_ / BK;

#pragma unroll
    for (int s = 0; s < 2; s++) {
        int kb = s * BK;
#pragma unroll
        for (int rr = 0; rr < 4; rr++) {
            cpa16(stA[rr] + s * SOFF, gA[rr] + kb);
            cpa16(stB[rr] + s * SOFF, gB[rr] + kb);
        }
        cpa_commit();
    }

    for (int kt = 0; kt < nk; kt++) {
        cpa_wait1();
        __syncthreads();
        if (kt + 2 < nk) {
            int kb = (kt + 2) * BK;
            uint32_t off = ((kt + 2) % 3) * SOFF;
#pragma unroll
            for (int rr = 0; rr < 4; rr++) {
                cpa16(stA[rr] + off, gA[rr] + kb);
                cpa16(stB[rr] + off, gB[rr] + kb);
            }
        }
        cpa_commit();

        uint32_t soff = (kt % 3) * SOFF;
#pragma unroll
        for (int ks = 0; ks < 4; ks++) {
            uint32_t koff = soff + ks * 32;
            uint32_t a[2][4];
            ldsm4(a[0], aAddr + koff);
            ldsm4(a[1], aAddr + koff + 16 * SROW * 4);
            uint32_t b2[4][4];
#pragma unroll
            for (int jp = 0; jp < 4; jp++)
                ldsm4(b2[jp], bAddr + koff + jp * (16 * SROW * 4));
#pragma unroll
            for (int im = 0; im < 2; im++)
#pragma unroll
                for (int jn = 0; jn < 8; jn++)
                    mma8(acc[im][jn], a[im], b2[jn >> 1][(jn & 1) * 2], b2[jn >> 1][(jn & 1) * 2 + 1]);
        }
    }

    int cg = 2 * (lane & 3);
#pragma unroll
    for (int im = 0; im < 2; im++) {
#pragma unroll
        for (int half = 0; half < 2; half++) {
            int i = m0 + wm + im * 16 + (lane >> 2) + half * 8;
            float* cp = Sb + (size_t)i * S_ + n0 + wn + cg;
#pragma unroll
            for (int jn = 0; jn < 8; jn++) {
                int j = n0 + wn + cg + jn * 8;
                float2 o;
                o.x = (j     > i) ? -1e30f : acc[im][jn][half * 2 + 0] * ATT_SCALE;
                o.y = (j + 1 > i) ? -1e30f : acc[im][jn][half * 2 + 1] * ATT_SCALE;
                *((float2*)(cp + jn * 8)) = o;
            }
        }
    }
}

// ==================== adaptive row softmax ====================
__global__ void softmax_k() {
    int r = blockIdx.x & (S_ - 1);
    float* row = g_att + (size_t)blockIdx.x * S_;
    int len = r + 1;
    int tid = threadIdx.x;
    float v[8];
    float mx = -1e30f;
#pragma unroll
    for (int i = 0; i < 8; i++) {
        int j = tid + i * 256;
        v[i] = (j < len) ? row[j] : -1e30f;
        mx = fmaxf(mx, v[i]);
    }
    __shared__ float red[32];
    for (int off = 16; off; off >>= 1) mx = fmaxf(mx, __shfl_xor_sync(0xffffffffu, mx, off));
    if ((tid & 31) == 0) red[tid >> 5] = mx;
    __syncthreads();
    if (tid < 32) {
        float m2 = (tid < 8) ? red[tid] : -1e38f;
        for (int off = 16; off; off >>= 1) m2 = fmaxf(m2, __shfl_xor_sync(0xffffffffu, m2, off));
        if (tid == 0) red[0] = m2;
    }
    __syncthreads();
    mx = red[0];
    float s = 0.f;
#pragma unroll
    for (int i = 0; i < 8; i++) { v[i] = __expf(v[i] - mx); s += v[i]; }
    __syncthreads();
    for (int off = 16; off; off >>= 1) s += __shfl_xor_sync(0xffffffffu, s, off);
    if ((tid & 31) == 0) red[tid >> 5] = s;
    __syncthreads();
    if (tid < 32) {
        float s2 = (tid < 8) ? red[tid] : 0.f;
        for (int off = 16; off; off >>= 1) s2 += __shfl_xor_sync(0xffffffffu, s2, off);
        if (tid == 0) red[0] = s2;
    }
    __syncthreads();
    float inv = 1.f / red[0];
#pragma unroll
    for (int i = 0; i < 8; i++) {
        int j = tid + i * 256;
        if (j < len) row[j] = v[i] * inv;
    }
    int kmax = ((r >> 7) + 1) << 7;
    for (int j = len + tid; j < kmax; j += 256) row[j] = 0.f;
}

// ==================== P @ V (tf32 MMA; epilogue emits fp16 for Wo) ====================
__global__ void __launch_bounds__(256)
attn_pv_mma(const float* __restrict__ V) {
    int bh = blockIdx.y, b = bh >> 4, h = bh & 15;
    int m0 = blockIdx.x * 128;
    const float* Pb = g_att + (size_t)bh * S_ * S_;
    const float* Vb = V + (size_t)b * S_ * H_ + h * HD_;
    __half* Ob = g_ao16 + (size_t)b * S_ * H_ + h * HD_;

    __shared__ uint32_t As[128][20];
    __shared__ uint32_t Bs[16][136];
    int tid = threadIdx.x;
    int lane = tid & 31, w = tid >> 5;
    int wm = (w & 3) * 32, wn = (w >> 2) * 64;
    int r1 = tid >> 2, c4 = (tid & 3) * 4;
    int kr = tid >> 5, nc4 = (tid & 31) * 4;

    const float* aP[2] = { Pb + (size_t)(m0 + r1) * S_ + c4,
                           Pb + (size_t)(m0 + r1 + 64) * S_ + c4 };

    float acc[2][8][4];
#pragma unroll
    for (int i = 0; i < 2; i++)
#pragma unroll
        for (int j = 0; j < 8; j++)
#pragma unroll
            for (int q = 0; q < 4; q++) acc[i][j][q] = 0.f;

    int kmax = m0 + 128;
    for (int kb = 0; kb < kmax; kb += 16) {
#pragma unroll
        for (int h2 = 0; h2 < 2; h2++) {
            float4 av = *(const float4*)(aP[h2] + kb);
            int rr = r1 + h2 * 64;
            As[rr][c4 + 0] = f2tf(av.x); As[rr][c4 + 1] = f2tf(av.y);
            As[rr][c4 + 2] = f2tf(av.z); As[rr][c4 + 3] = f2tf(av.w);
            float4 bv = *(const float4*)(Vb + (size_t)(kb + kr + h2 * 8) * H_ + nc4);
            int kk = kr + h2 * 8;
            Bs[kk][nc4 + 0] = f2tf(bv.x); Bs[kk][nc4 + 1] = f2tf(bv.y);
            Bs[kk][nc4 + 2] = f2tf(bv.z); Bs[kk][nc4 + 3] = f2tf(bv.w);
        }
        __syncthreads();
#pragma unroll
        for (int ks = 0; ks < 2; ks++) {
            int k0 = ks * 8 + (lane & 3);
            uint32_t af[2][4];
#pragma unroll
            for (int im = 0; im < 2; im++) {
                int mr = wm + im * 16 + (lane >> 2);
                af[im][0] = As[mr][k0];     af[im][1] = As[mr + 8][k0];
                af[im][2] = As[mr][k0 + 4]; af[im][3] = As[mr + 8][k0 + 4];
            }
#pragma unroll
            for (int jn = 0; jn < 8; jn++) {
                int nr = wn + jn * 8 + (lane >> 2);
                uint32_t b0 = Bs[k0][nr], b1 = Bs[k0 + 4][nr];
                mma8(acc[0][jn], af[0], b0, b1);
                mma8(acc[1][jn], af[1], b0, b1);
            }
        }
        __syncthreads();
    }

    int cg = 2 * (lane & 3);
#pragma unroll
    for (int im = 0; im < 2; im++) {
#pragma unroll
        for (int half = 0; half < 2; half++) {
            int m = m0 + wm + im * 16 + (lane >> 2) + half * 8;
            __half* cp = Ob + (size_t)m * H_ + wn + cg;
#pragma unroll
            for (int jn = 0; jn < 8; jn++) {
                *((__half2*)(cp + jn * 8)) =
                    __floats2half2_rn(acc[im][jn][half * 2 + 0], acc[im][jn][half * 2 + 1]);
            }
        }
    }
}

// ==================== router (EXACT fp32 input) ====================
__global__ void router_k(const float* __restrict__ xn2e, const float* __restrict__ Wr) {
    int t = blockIdx.x * (blockDim.x >> 5) + (threadIdx.x >> 5);
    if (t >= T_) return;
    int lane = threadIdx.x & 31;
    const float* xr = xn2e + (size_t)t * H_;
    float s[NE_];
#pragma unroll
    for (int e = 0; e < NE_; e++) s[e] = 0.f;
    for (int j = lane; j < H_; j += 32) {
        float xv = xr[j];
#pragma unroll
        for (int e = 0; e < NE_; e++) s[e] += xv * Wr[e * H_ + j];
    }
#pragma unroll
    for (int e = 0; e < NE_; e++)
        for (int off = 16; off; off >>= 1) s[e] += __shfl_xor_sync(0xffffffffu, s[e], off);
    if (lane == 0) {
        int b0 = 0;
#pragma unroll
        for (int e = 1; e < NE_; e++) if (s[e] > s[b0]) b0 = e;
        int b1 = -1;
#pragma unroll
        for (int e = 0; e < NE_; e++) {
            if (e == b0) continue;
            if (b1 < 0 || s[e] > s[b1]) b1 = e;
        }
        float m = s[b0];
        float e0 = __expf(s[b0] - m), e1 = __expf(s[b1] - m);
        float inv = 1.f / (e0 + e1);
        int pos = atomicAdd(&g_cnt[b0], 1);
        g_tok[b0 * T_ + pos] = t; g_wt[b0 * T_ + pos] = e0 * inv;
        pos = atomicAdd(&g_cnt[b1], 1);
        g_tok[b1 * T_ + pos] = t; g_wt[b1 * T_ + pos] = e1 * inv;
    }
}

// ==================== host ====================
extern "C" void kernel_launch(void* const* d_in, const int* in_sizes, int n_in,
                              void* d_out, int out_size) {
    const float* x    = (const float*)d_in[0];
    const float* Wq   = (const float*)d_in[1];
    const float* Wk   = (const float*)d_in[2];
    const float* Wv   = (const float*)d_in[3];
    const float* Wo   = (const float*)d_in[4];
    const float* wln1 = (const float*)d_in[5];
    const float* wln2 = (const float*)d_in[6];
    const float* Wr   = (const float*)d_in[7];
    const float* Wg   = (const float*)d_in[8];
    const float* Wu   = (const float*)d_in[9];
    const float* Wd   = (const float*)d_in[10];
    float* out = (float*)d_out;

    float *p_q, *p_k, *p_v, *p_hg, *p_hu, *p_wt;
    __half *p_xn16, *p_ao16, *p_xn216, *p_hg16, *p_w16;
    int *p_tok, *p_cnt;
    cudaGetSymbolAddress((void**)&p_q,     g_q);
    cudaGetSymbolAddress((void**)&p_k,     g_k);
    cudaGetSymbolAddress((void**)&p_v,     g_v);
    cudaGetSymbolAddress((void**)&p_hg,    g_hg);
    cudaGetSymbolAddress((void**)&p_hu,    g_hu);
    cudaGetSymbolAddress((void**)&p_xn16,  g_xn16);
    cudaGetSymbolAddress((void**)&p_ao16,  g_ao16);
    cudaGetSymbolAddress((void**)&p_xn216, g_xn216);
    cudaGetSymbolAddress((void**)&p_hg16,  g_hg16);
    cudaGetSymbolAddress((void**)&p_w16,   g_w16);
    cudaGetSymbolAddress((void**)&p_tok,   g_tok);
    cudaGetSymbolAddress((void**)&p_wt,    g_wt);
    cudaGetSymbolAddress((void**)&p_cnt,   g_cnt);

    static int smem_set = 0;
    if (!smem_set) {
        cudaFuncSetAttribute(hgemm, cudaFuncAttributeMaxDynamicSharedMemorySize, H_SMEM);
        cudaFuncSetAttribute(attn_score_mma2, cudaFuncAttributeMaxDynamicSharedMemorySize, SMEM_BYTES3);
        smem_set = 1;
    }

    zero_cnt_k<<<1, 32>>>();

    // ---- weight conversion fp32 -> fp16 ----
    cvt16_k<<<2048, 256>>>(Wq, p_w16 + OFF_WQ, (size_t)H_ * H_ / 4);
    cvt16_k<<<2048, 256>>>(Wk, p_w16 + OFF_WK, (size_t)H_ * H_ / 4);
    cvt16_k<<<2048, 256>>>(Wv, p_w16 + OFF_WV, (size_t)H_ * H_ / 4);
    cvt16_k<<<2048, 256>>>(Wo, p_w16 + OFF_WO, (size_t)H_ * H_ / 4);
    cvt16_k<<<4096, 256>>>(Wg, p_w16 + OFF_WG, (size_t)NE_ * I_ * H_ / 4);
    cvt16_k<<<4096, 256>>>(Wu, p_w16 + OFF_WU, (size_t)NE_ * I_ * H_ / 4);
    cvt16_k<<<4096, 256>>>(Wd, p_w16 + OFF_WD, (size_t)NE_ * H_ * I_ / 4);

    rmsnorm_k<<<T_, 256>>>(x, wln1, p_xn16, nullptr);

    // QKV fused; outputs fp32 rounded to tf32 (attention feed)
    {
        GArgs a = {};
        a.A = p_xn16;
        a.B0 = p_w16 + OFF_WQ; a.B1 = p_w16 + OFF_WK; a.B2 = p_w16 + OFF_WV;
        a.C0 = p_q; a.C1 = p_k; a.C2 = p_v;
        a.M = T_; a.N = H_; a.K = H_; a.lda = H_; a.ldb = H_; a.ldc = H_;
        a.mode = 0; a.roundC = 1;
        hgemm<<<dim3(H_ / 128, T_ / 128, 3), 256, H_SMEM>>>(a);
    }

    attn_score_mma2<<<dim3(S_ / 128, S_ / 128, B_ * NH_), 256, SMEM_BYTES3>>>(p_q, p_k);
    softmax_k<<<B_ * NH_ * S_, 256>>>();
    attn_pv_mma<<<dim3(S_ / 128, B_ * NH_), 256>>>(p_v);

    // Wo projection + fused residual
    {
        GArgs a = {};
        a.A = p_ao16; a.B0 = p_w16 + OFF_WO; a.C0 = out;
        a.resid = x;
        a.M = T_; a.N = H_; a.K = H_; a.lda = H_; a.ldb = H_; a.ldc = H_;
        a.mode = 0;
        hgemm<<<dim3(H_ / 128, T_ / 128, 1), 256, H_SMEM>>>(a);
    }

    // ln2: fp16 -> xn216 (GEMM A), exact fp32 -> g_q (router; buffer reused)
    rmsnorm_k<<<T_, 256>>>(out, wln2, p_xn216, p_q);
    router_k<<<T_ / 8, 256>>>(p_q, Wr);

    // MoE gate+up (gathered A)
    {
        GArgs a = {};
        a.A = p_xn216;
        a.B0 = p_w16 + OFF_WG; a.B1 = p_w16 + OFF_WU;
        a.C0 = p_hg; a.C1 = p_hu;
        a.M = T_; a.N = I_; a.K = H_; a.lda = H_; a.ldb = H_; a.ldc = I_;
        a.tok = p_tok; a.cntp = p_cnt;
        a.bStride = (size_t)I_ * H_; a.cStride = (size_t)T_ * I_;
        a.mode = 1;
        hgemm<<<dim3(I_ / 128, T_ / 128, 2 * NE_), 256, H_SMEM>>>(a);
    }

    swiglu_all_k<<<dim3(512, NE_), 256>>>(p_hg, p_hu, p_hg16);

    // MoE down: atomic scatter-add into out
    {
        GArgs a = {};
        a.A = p_hg16; a.B0 = p_w16 + OFF_WD; a.C0 = out;
        a.M = T_; a.N = H_; a.K = I_; a.lda = I_; a.ldb = I_; a.ldc = H_;
        a.tok = p_tok; a.wt = p_wt; a.cntp = p_cnt;
        a.aStride = (size_t)T_ * I_; a.bStride = (size_t)H_ * I_;
        a.mode = 2;
        hgemm<<<dim3(H_ / 128, T_ / 128, NE_), 256, H_SMEM>>>(a);
    }
}

// round 10
// speedup vs baseline: 1.6905x; 1.1207x over previous
#include <cuda_runtime.h>
#include <cuda_fp16.h>
#include <math.h>
#include <stdint.h>

#define B_   2
#define S_   2048
#define H_   2048
#define NH_  16
#define HD_  128
#define NE_  8
#define I_   4096
#define T_   (B_*S_)
#define EPS_ 1e-5f
#define ATT_SCALE 0.08838834764831845f

// -------------------- scratch --------------------
__device__ float  g_att[(size_t)B_*NH_*S_*S_];     // fp32 scores
__device__ float  g_hg [(size_t)NE_*T_*I_];        // aliased: P(half) during attn; gate/up pre-act (2x half) in MoE
__device__ float  g_rex[(size_t)T_*H_];            // ln2 exact (router)
__device__ __half g_q16  [(size_t)T_*H_];
__device__ __half g_k16  [(size_t)T_*H_];
__device__ __half g_vt16 [(size_t)B_*NH_*HD_*S_];  // V transposed: [b,h][d][s]
__device__ __half g_xn16 [(size_t)T_*H_];
__device__ __half g_ao16 [(size_t)T_*H_];
__device__ __half g_xn216[(size_t)T_*H_];
__device__ __half g_hg16 [(size_t)NE_*T_*I_];      // swiglu out (down A)
#define OFF_WQ ((size_t)0)
#define OFF_WK ((size_t)H_*H_)
#define OFF_WV ((size_t)2*H_*H_)
#define OFF_WO ((size_t)3*H_*H_)
#define OFF_WG ((size_t)4*H_*H_)
#define OFF_WU (OFF_WG + (size_t)NE_*I_*H_)
#define OFF_WD (OFF_WU + (size_t)NE_*I_*H_)
#define W16_TOTAL (OFF_WD + (size_t)NE_*H_*I_)
__device__ __half g_w16[W16_TOTAL];
__device__ int   g_tok[NE_*T_];
__device__ float g_wt [NE_*T_];
__device__ int   g_cnt[NE_];

// -------------------- helpers --------------------
__device__ __forceinline__ void mma16h(float* c, const uint32_t* a, uint32_t b0, uint32_t b1) {
    asm volatile("mma.sync.aligned.m16n8k16.row.col.f32.f16.f16.f32 "
        "{%0,%1,%2,%3},{%4,%5,%6,%7},{%8,%9},{%0,%1,%2,%3};"
        : "+f"(c[0]), "+f"(c[1]), "+f"(c[2]), "+f"(c[3])
        : "r"(a[0]), "r"(a[1]), "r"(a[2]), "r"(a[3]), "r"(b0), "r"(b1));
}
__device__ __forceinline__ void ldsm4(uint32_t* r, uint32_t addr) {
    asm volatile("ldmatrix.sync.aligned.m8n8.x4.shared.b16 {%0,%1,%2,%3},[%4];"
        : "=r"(r[0]), "=r"(r[1]), "=r"(r[2]), "=r"(r[3]) : "r"(addr));
}
__device__ __forceinline__ void cpa16(uint32_t dst, const void* src) {
    asm volatile("cp.async.cg.shared.global [%0], [%1], 16;" :: "r"(dst), "l"(src));
}
__device__ __forceinline__ void cpa_commit() { asm volatile("cp.async.commit_group;"); }
__device__ __forceinline__ void cpa_wait1()  { asm volatile("cp.async.wait_group 1;" ::: "memory"); }
__device__ __forceinline__ uint32_t smem_u32(const void* p) {
    uint32_t a; asm("{ .reg .u64 t; cvta.to.shared.u64 t, %1; cvt.u32.u64 %0, t; }"
                    : "=r"(a) : "l"(p));
    return a;
}

#define HROWB 80
#define H_STG 3
#define H_STAGE (128*HROWB)
#define H_SMEM (2*H_STG*H_STAGE)      // 61440 B

// -------------------- small kernels --------------------
__global__ void zero_cnt_k() { if (threadIdx.x < NE_) g_cnt[threadIdx.x] = 0; }

__global__ void cvt16_k(const float* __restrict__ s, __half* __restrict__ d, size_t n4) {
    size_t stride = (size_t)gridDim.x * blockDim.x;
    const float4* S = (const float4*)s;
    __half2* D = (__half2*)d;
    for (size_t i = (size_t)blockIdx.x * blockDim.x + threadIdx.x; i < n4; i += stride) {
        float4 v = S[i];
        D[2 * i]     = __floats2half2_rn(v.x, v.y);
        D[2 * i + 1] = __floats2half2_rn(v.z, v.w);
    }
}

__global__ void rmsnorm_k(const float* __restrict__ x, const float* __restrict__ w,
                          __half* __restrict__ o16, float* __restrict__ o_exact) {
    int t = blockIdx.x;
    const float* xr = x + (size_t)t * H_;
    float s = 0.f;
    for (int j = threadIdx.x; j < H_; j += blockDim.x) { float v = xr[j]; s += v * v; }
    __shared__ float red[32];
    for (int off = 16; off; off >>= 1) s += __shfl_xor_sync(0xffffffffu, s, off);
    if ((threadIdx.x & 31) == 0) red[threadIdx.x >> 5] = s;
    __syncthreads();
    if (threadIdx.x < 32) {
        float v = (threadIdx.x < (blockDim.x >> 5)) ? red[threadIdx.x] : 0.f;
        for (int off = 16; off; off >>= 1) v += __shfl_xor_sync(0xffffffffu, v, off);
        if (threadIdx.x == 0) red[0] = v;
    }
    __syncthreads();
    float inv = rsqrtf(red[0] / (float)H_ + EPS_);
    __half* orow = o16 + (size_t)t * H_;
    if (o_exact) {
        float* erow = o_exact + (size_t)t * H_;
        for (int j = threadIdx.x; j < H_; j += blockDim.x) {
            float v = xr[j] * inv * w[j];
            erow[j] = v;
            orow[j] = __float2half_rn(v);
        }
    } else {
        for (int j = threadIdx.x; j < H_; j += blockDim.x)
            orow[j] = __float2half_rn(xr[j] * inv * w[j]);
    }
}

// swiglu: fp16 pre-acts in, fp16 out
__global__ void swiglu_all_k(const __half* __restrict__ hgp, const __half* __restrict__ hup,
                             __half* __restrict__ ho) {
    int e = blockIdx.y;
    int cnt = g_cnt[e];
    const __half2* G = (const __half2*)(hgp + (size_t)e * T_ * I_);
    const __half2* U = (const __half2*)(hup + (size_t)e * T_ * I_);
    __half2* O = (__half2*)(ho + (size_t)e * T_ * I_);
    size_t total = (size_t)cnt * (I_ / 2);
    size_t stride = (size_t)gridDim.x * blockDim.x;
    for (size_t i = (size_t)blockIdx.x * blockDim.x + threadIdx.x; i < total; i += stride) {
        float2 g = __half22float2(G[i]);
        float2 u = __half22float2(U[i]);
        float a = g.x / (1.f + __expf(-g.x)) * u.x;
        float b = g.y / (1.f + __expf(-g.y)) * u.y;
        O[i] = __floats2half2_rn(a, b);
    }
}

// ==================== fp16 MMA GEMM ====================
// Mode 0 + qkv: z in {0,1}: half out to H0/H1; z==2: V transposed into H2 [b,h][d][s].
// Mode 0 (no qkv): fp32 out C0, optional resid.
// Mode 1: z = expert*2+{gate,up}; gathered A; half out to H0/H1 (+e*cStride).
// Mode 2: z = expert; dense per-expert A; atomic fp32 scatter-add.
struct GArgs {
    const __half* A;
    const __half* B0; const __half* B1; const __half* B2;
    float* C0;
    __half* H0; __half* H1; __half* H2;
    const float* resid;
    int M, N, K, lda, ldb, ldc;
    const int* tok; const float* wt; const int* cntp;
    size_t aStride, bStride, cStride;
    int mode;
    int qkv;
};

__global__ void __launch_bounds__(256, 2)
hgemm(const GArgs args) {
    int z = blockIdx.z;
    const __half* A = args.A;
    const __half* B;
    const int* a_idx = nullptr; const int* c_idx = nullptr; const float* c_w = nullptr;
    int cnt = args.M;
    int ep_mode;          // 0=fp32 (resid opt), 1=half H, 2=vtrans, 3=atomic
    float* Cf = args.C0;
    __half* Ch = nullptr;

    if (args.mode == 0) {
        B = (z == 0) ? args.B0 : (z == 1 ? args.B1 : args.B2);
        if (args.qkv) {
            if (z < 2) { Ch = z ? args.H1 : args.H0; ep_mode = 1; }
            else ep_mode = 2;
        } else ep_mode = 0;
    } else if (args.mode == 1) {
        int e = z >> 1;
        B = ((z & 1) ? args.B1 : args.B0) + (size_t)e * args.bStride;
        Ch = ((z & 1) ? args.H1 : args.H0) + (size_t)e * args.cStride;
        a_idx = args.tok + e * T_;
        cnt = args.cntp[e];
        ep_mode = 1;
    } else {
        int e = z;
        A = args.A + (size_t)e * args.aStride;
        B = args.B0 + (size_t)e * args.bStride;
        c_idx = args.tok + e * T_;
        c_w = args.wt + e * T_;
        cnt = args.cntp[e];
        ep_mode = 3;
    }

    int m0 = blockIdx.y * 128, n0 = blockIdx.x * 128;
    if (m0 >= cnt) return;

    extern __shared__ char smem[];
    uint32_t sA = smem_u32(smem);
    uint32_t sB = sA + H_STG * H_STAGE;

    int tid = threadIdx.x;
    int lane = tid & 31, w = tid >> 5;
    int wm = (w & 3) * 32, wn = (w >> 2) * 64;

    int lrow = tid >> 2;
    int lch  = tid & 3;
    const __half* gA[2]; const __half* gB[2];
    uint32_t stA[2], stB[2];
#pragma unroll
    for (int rr = 0; rr < 2; rr++) {
        int r = lrow + rr * 64;
        int mr = m0 + r;
        int grow = a_idx ? ((mr < cnt) ? a_idx[mr] : 0) : mr;
        gA[rr] = A + (size_t)grow * args.lda + lch * 8;
        gB[rr] = B + (size_t)(n0 + r) * args.ldb + lch * 8;
        stA[rr] = sA + r * HROWB + lch * 16;
        stB[rr] = sB + r * HROWB + lch * 16;
    }

    uint32_t aAddr = sA + (wm + (lane & 15)) * HROWB + ((lane >> 4) & 1) * 16;
    uint32_t bAddr = sB + (wn + (lane & 7) + 8 * ((lane >> 4) & 1)) * HROWB
                        + ((lane >> 3) & 1) * 16;

    float acc[2][8][4];
#pragma unroll
    for (int i = 0; i < 2; i++)
#pragma unroll
        for (int j = 0; j < 8; j++)
#pragma unroll
            for (int q = 0; q < 4; q++) acc[i][j][q] = 0.f;

    int nk = args.K / 32;

#pragma unroll
    for (int s = 0; s < 2; s++) {
#pragma unroll
        for (int rr = 0; rr < 2; rr++) {
            cpa16(stA[rr] + s * H_STAGE, gA[rr] + s * 32);
            cpa16(stB[rr] + s * H_STAGE, gB[rr] + s * 32);
        }
        cpa_commit();
    }

    for (int kt = 0; kt < nk; kt++) {
        cpa_wait1();
        __syncthreads();
        if (kt + 2 < nk) {
            int kb = (kt + 2) * 32;
            uint32_t off = ((kt + 2) % H_STG) * H_STAGE;
#pragma unroll
            for (int rr = 0; rr < 2; rr++) {
                cpa16(stA[rr] + off, gA[rr] + kb);
                cpa16(stB[rr] + off, gB[rr] + kb);
            }
        }
        cpa_commit();

        uint32_t soff = (kt % H_STG) * H_STAGE;
#pragma unroll
        for (int ks = 0; ks < 2; ks++) {
            uint32_t koff = soff + ks * 32;
            uint32_t a[2][4];
            ldsm4(a[0], aAddr + koff);
            ldsm4(a[1], aAddr + koff + 16 * HROWB);
            uint32_t b[4][4];
#pragma unroll
            for (int jp = 0; jp < 4; jp++)
                ldsm4(b[jp], bAddr + koff + jp * (16 * HROWB));
#pragma unroll
            for (int im = 0; im < 2; im++)
#pragma unroll
                for (int jn = 0; jn < 8; jn++)
                    mma16h(acc[im][jn], a[im], b[jn >> 1][(jn & 1) * 2], b[jn >> 1][(jn & 1) * 2 + 1]);
        }
        __syncthreads();
    }

    int cg = 2 * (lane & 3);
#pragma unroll
    for (int im = 0; im < 2; im++) {
#pragma unroll
        for (int half = 0; half < 2; half++) {
            int m = m0 + wm + im * 16 + (lane >> 2) + half * 8;
            if (m >= cnt) continue;
            if (ep_mode == 3) {
                int tr = c_idx[m]; float wv = c_w[m];
                float* cp = Cf + (size_t)tr * args.ldc + n0 + wn + cg;
#pragma unroll
                for (int jn = 0; jn < 8; jn++) {
                    atomicAdd(cp + jn * 8,     wv * acc[im][jn][half * 2 + 0]);
                    atomicAdd(cp + jn * 8 + 1, wv * acc[im][jn][half * 2 + 1]);
                }
            } else if (ep_mode == 1) {
                __half* cp = Ch + (size_t)m * args.ldc + n0 + wn + cg;
#pragma unroll
                for (int jn = 0; jn < 8; jn++)
                    *((__half2*)(cp + jn * 8)) =
                        __floats2half2_rn(acc[im][jn][half * 2 + 0], acc[im][jn][half * 2 + 1]);
            } else if (ep_mode == 2) {
                int bb = m >> 11, ss = m & (S_ - 1);
#pragma unroll
                for (int jn = 0; jn < 8; jn++) {
                    int col = n0 + wn + cg + jn * 8;
                    int hh = col >> 7, d = col & 127;
                    size_t base = ((size_t)(bb * NH_ + hh) * HD_ + d) * S_ + ss;
                    args.H2[base]      = __float2half_rn(acc[im][jn][half * 2 + 0]);
                    args.H2[base + S_] = __float2half_rn(acc[im][jn][half * 2 + 1]);
                }
            } else {
                float* cp = Cf + (size_t)m * args.ldc + n0 + wn + cg;
                if (args.resid) {
                    const float* rp = args.resid + (size_t)m * args.ldc + n0 + wn + cg;
#pragma unroll
                    for (int jn = 0; jn < 8; jn++) {
                        float2 r = *((const float2*)(rp + jn * 8));
                        float2 o;
                        o.x = acc[im][jn][half * 2 + 0] + r.x;
                        o.y = acc[im][jn][half * 2 + 1] + r.y;
                        *((float2*)(cp + jn * 8)) = o;
                    }
                } else {
#pragma unroll
                    for (int jn = 0; jn < 8; jn++) {
                        float2 o;
                        o.x = acc[im][jn][half * 2 + 0];
                        o.y = acc[im][jn][half * 2 + 1];
                        *((float2*)(cp + jn * 8)) = o;
                    }
                }
            }
        }
    }
}

// ==================== causal scores (fp16 pipelined) ====================
__global__ void __launch_bounds__(256, 2)
attn_score_h(const __half* __restrict__ Q, const __half* __restrict__ K16) {
    int bh = blockIdx.z, b = bh >> 4, h = bh & 15;
    int m0 = blockIdx.y * 128, n0 = blockIdx.x * 128;
    if (n0 > m0) return;

    const __half* Qb = Q + (size_t)b * S_ * H_ + h * HD_;
    const __half* Kb = K16 + (size_t)b * S_ * H_ + h * HD_;
    float* Sb = g_att + (size_t)bh * S_ * S_;

    extern __shared__ char smem[];
    uint32_t sA = smem_u32(smem);
    uint32_t sB = sA + H_STG * H_STAGE;

    int tid = threadIdx.x;
    int lane = tid & 31, w = tid >> 5;
    int wm = (w & 3) * 32, wn = (w >> 2) * 64;

    int lrow = tid >> 2, lch = tid & 3;
    const __half* gA[2]; const __half* gB[2];
    uint32_t stA[2], stB[2];
#pragma unroll
    for (int rr = 0; rr < 2; rr++) {
        int r = lrow + rr * 64;
        gA[rr] = Qb + (size_t)(m0 + r) * H_ + lch * 8;
        gB[rr] = Kb + (size_t)(n0 + r) * H_ + lch * 8;
        stA[rr] = sA + r * HROWB + lch * 16;
        stB[rr] = sB + r * HROWB + lch * 16;
    }

    uint32_t aAddr = sA + (wm + (lane & 15)) * HROWB + ((lane >> 4) & 1) * 16;
    uint32_t bAddr = sB + (wn + (lane & 7) + 8 * ((lane >> 4) & 1)) * HROWB
                        + ((lane >> 3) & 1) * 16;

    float acc[2][8][4];
#pragma unroll
    for (int i = 0; i < 2; i++)
#pragma unroll
        for (int j = 0; j < 8; j++)
#pragma unroll
            for (int q = 0; q < 4; q++) acc[i][j][q] = 0.f;

    const int nk = HD_ / 32;   // 4

#pragma unroll
    for (int s = 0; s < 2; s++) {
#pragma unroll
        for (int rr = 0; rr < 2; rr++) {
            cpa16(stA[rr] + s * H_STAGE, gA[rr] + s * 32);
            cpa16(stB[rr] + s * H_STAGE, gB[rr] + s * 32);
        }
        cpa_commit();
    }

    for (int kt = 0; kt < nk; kt++) {
        cpa_wait1();
        __syncthreads();
        if (kt + 2 < nk) {
            int kb = (kt + 2) * 32;
            uint32_t off = ((kt + 2) % H_STG) * H_STAGE;
#pragma unroll
            for (int rr = 0; rr < 2; rr++) {
                cpa16(stA[rr] + off, gA[rr] + kb);
                cpa16(stB[rr] + off, gB[rr] + kb);
            }
        }
        cpa_commit();

        uint32_t soff = (kt % H_STG) * H_STAGE;
#pragma unroll
        for (int ks = 0; ks < 2; ks++) {
            uint32_t koff = soff + ks * 32;
            uint32_t a[2][4];
            ldsm4(a[0], aAddr + koff);
            ldsm4(a[1], aAddr + koff + 16 * HROWB);
            uint32_t b2[4][4];
#pragma unroll
            for (int jp = 0; jp < 4; jp++)
                ldsm4(b2[jp], bAddr + koff + jp * (16 * HROWB));
#pragma unroll
            for (int im = 0; im < 2; im++)
#pragma unroll
                for (int jn = 0; jn < 8; jn++)
                    mma16h(acc[im][jn], a[im], b2[jn >> 1][(jn & 1) * 2], b2[jn >> 1][(jn & 1) * 2 + 1]);
        }
        __syncthreads();
    }

    int cg = 2 * (lane & 3);
#pragma unroll
    for (int im = 0; im < 2; im++) {
#pragma unroll
        for (int half = 0; half < 2; half++) {
            int i = m0 + wm + im * 16 + (lane >> 2) + half * 8;
            float* cp = Sb + (size_t)i * S_ + n0 + wn + cg;
#pragma unroll
            for (int jn = 0; jn < 8; jn++) {
                int j = n0 + wn + cg + jn * 8;
                float2 o;
                o.x = (j     > i) ? -1e30f : acc[im][jn][half * 2 + 0] * ATT_SCALE;
                o.y = (j + 1 > i) ? -1e30f : acc[im][jn][half * 2 + 1] * ATT_SCALE;
                *((float2*)(cp + jn * 8)) = o;
            }
        }
    }
}

// ==================== adaptive row softmax: fp32 scores in, fp16 P out ====================
__global__ void softmax_k(__half* __restrict__ P) {
    int r = blockIdx.x & (S_ - 1);
    const float* row = g_att + (size_t)blockIdx.x * S_;
    __half* prow = P + (size_t)blockIdx.x * S_;
    int len = r + 1;
    int tid = threadIdx.x;
    float v[8];
    float mx = -1e30f;
#pragma unroll
    for (int i = 0; i < 8; i++) {
        int j = tid + i * 256;
        v[i] = (j < len) ? row[j] : -1e30f;
        mx = fmaxf(mx, v[i]);
    }
    __shared__ float red[32];
    for (int off = 16; off; off >>= 1) mx = fmaxf(mx, __shfl_xor_sync(0xffffffffu, mx, off));
    if ((tid & 31) == 0) red[tid >> 5] = mx;
    __syncthreads();
    if (tid < 32) {
        float m2 = (tid < 8) ? red[tid] : -1e38f;
        for (int off = 16; off; off >>= 1) m2 = fmaxf(m2, __shfl_xor_sync(0xffffffffu, m2, off));
        if (tid == 0) red[0] = m2;
    }
    __syncthreads();
    mx = red[0];
    float s = 0.f;
#pragma unroll
    for (int i = 0; i < 8; i++) { v[i] = __expf(v[i] - mx); s += v[i]; }
    __syncthreads();
    for (int off = 16; off; off >>= 1) s += __shfl_xor_sync(0xffffffffu, s, off);
    if ((tid & 31) == 0) red[tid >> 5] = s;
    __syncthreads();
    if (tid < 32) {
        float s2 = (tid < 8) ? red[tid] : 0.f;
        for (int off = 16; off; off >>= 1) s2 += __shfl_xor_sync(0xffffffffu, s2, off);
        if (tid == 0) red[0] = s2;
    }
    __syncthreads();
    float inv = 1.f / red[0];
#pragma unroll
    for (int i = 0; i < 8; i++) {
        int j = tid + i * 256;
        if (j < len) prow[j] = __float2half_rn(v[i] * inv);
    }
    int kmax = ((r >> 7) + 1) << 7;
    for (int j = len + tid; j < kmax; j += 256) prow[j] = __float2half_rn(0.f);
}

// ==================== P @ Vt (fp16 pipelined, causal-truncated) ====================
__global__ void __launch_bounds__(256, 2)
attn_pv_h(const __half* __restrict__ P, const __half* __restrict__ Vt,
          __half* __restrict__ O) {
    int bh = blockIdx.y, b = bh >> 4, h = bh & 15;
    int m0 = blockIdx.x * 128;
    const __half* Pb = P + (size_t)bh * S_ * S_;
    const __half* Vb = Vt + (size_t)bh * HD_ * S_;

    extern __shared__ char smem[];
    uint32_t sA = smem_u32(smem);
    uint32_t sB = sA + H_STG * H_STAGE;

    int tid = threadIdx.x;
    int lane = tid & 31, w = tid >> 5;
    int wm = (w & 3) * 32, wn = (w >> 2) * 64;

    int lrow = tid >> 2, lch = tid & 3;
    const __half* gA[2]; const __half* gB[2];
    uint32_t stA[2], stB[2];
#pragma unroll
    for (int rr = 0; rr < 2; rr++) {
        int r = lrow + rr * 64;
        gA[rr] = Pb + (size_t)(m0 + r) * S_ + lch * 8;
        gB[rr] = Vb + (size_t)r * S_ + lch * 8;     // B rows = d (128), K-major along s
        stA[rr] = sA + r * HROWB + lch * 16;
        stB[rr] = sB + r * HROWB + lch * 16;
    }

    uint32_t aAddr = sA + (wm + (lane & 15)) * HROWB + ((lane >> 4) & 1) * 16;
    uint32_t bAddr = sB + (wn + (lane & 7) + 8 * ((lane >> 4) & 1)) * HROWB
                        + ((lane >> 3) & 1) * 16;

    float acc[2][8][4];
#pragma unroll
    for (int i = 0; i < 2; i++)
#pragma unroll
        for (int j = 0; j < 8; j++)
#pragma unroll
            for (int q = 0; q < 4; q++) acc[i][j][q] = 0.f;

    int nk = (m0 + 128) / 32;

#pragma unroll
    for (int s = 0; s < 2; s++) {
#pragma unroll
        for (int rr = 0; rr < 2; rr++) {
            cpa16(stA[rr] + s * H_STAGE, gA[rr] + s * 32);
            cpa16(stB[rr] + s * H_STAGE, gB[rr] + s * 32);
        }
        cpa_commit();
    }

    for (int kt = 0; kt < nk; kt++) {
        cpa_wait1();
        __syncthreads();
        if (kt + 2 < nk) {
            int kb = (kt + 2) * 32;
            uint32_t off = ((kt + 2) % H_STG) * H_STAGE;
#pragma unroll
            for (int rr = 0; rr < 2; rr++) {
                cpa16(stA[rr] + off, gA[rr] + kb);
                cpa16(stB[rr] + off, gB[rr] + kb);
            }
        }
        cpa_commit();

        uint32_t soff = (kt % H_STG) * H_STAGE;
#pragma unroll
        for (int ks = 0; ks < 2; ks++) {
            uint32_t koff = soff + ks * 32;
            uint32_t a[2][4];
            ldsm4(a[0], aAddr + koff);
            ldsm4(a[1], aAddr + koff + 16 * HROWB);
            uint32_t b2[4][4];
#pragma unroll
            for (int jp = 0; jp < 4; jp++)
                ldsm4(b2[jp], bAddr + koff + jp * (16 * HROWB));
#pragma unroll
            for (int im = 0; im < 2; im++)
#pragma unroll
                for (int jn = 0; jn < 8; jn++)
                    mma16h(acc[im][jn], a[im], b2[jn >> 1][(jn & 1) * 2], b2[jn >> 1][(jn & 1) * 2 + 1]);
        }
        __syncthreads();
    }

    int cg = 2 * (lane & 3);
#pragma unroll
    for (int im = 0; im < 2; im++) {
#pragma unroll
        for (int half = 0; half < 2; half++) {
            int m = m0 + wm + im * 16 + (lane >> 2) + half * 8;
            __half* cp = O + (size_t)(b * S_ + m) * H_ + h * HD_ + wn + cg;
#pragma unroll
            for (int jn = 0; jn < 8; jn++)
                *((__half2*)(cp + jn * 8)) =
                    __floats2half2_rn(acc[im][jn][half * 2 + 0], acc[im][jn][half * 2 + 1]);
        }
    }
}

// ==================== router (EXACT fp32 input) ====================
__global__ void router_k(const float* __restrict__ xn2e, const float* __restrict__ Wr) {
    int t = blockIdx.x * (blockDim.x >> 5) + (threadIdx.x >> 5);
    if (t >= T_) return;
    int lane = threadIdx.x & 31;
    const float* xr = xn2e + (size_t)t * H_;
    float s[NE_];
#pragma unroll
    for (int e = 0; e < NE_; e++) s[e] = 0.f;
    for (int j = lane; j < H_; j += 32) {
        float xv = xr[j];
#pragma unroll
        for (int e = 0; e < NE_; e++) s[e] += xv * Wr[e * H_ + j];
    }
#pragma unroll
    for (int e = 0; e < NE_; e++)
        for (int off = 16; off; off >>= 1) s[e] += __shfl_xor_sync(0xffffffffu, s[e], off);
    if (lane == 0) {
        int b0 = 0;
#pragma unroll
        for (int e = 1; e < NE_; e++) if (s[e] > s[b0]) b0 = e;
        int b1 = -1;
#pragma unroll
        for (int e = 0; e < NE_; e++) {
            if (e == b0) continue;
            if (b1 < 0 || s[e] > s[b1]) b1 = e;
        }
        float m = s[b0];
        float e0 = __expf(s[b0] - m), e1 = __expf(s[b1] - m);
        float inv = 1.f / (e0 + e1);
        int pos = atomicAdd(&g_cnt[b0], 1);
        g_tok[b0 * T_ + pos] = t; g_wt[b0 * T_ + pos] = e0 * inv;
        pos = atomicAdd(&g_cnt[b1], 1);
        g_tok[b1 * T_ + pos] = t; g_wt[b1 * T_ + pos] = e1 * inv;
    }
}

// ==================== host ====================
extern "C" void kernel_launch(void* const* d_in, const int* in_sizes, int n_in,
                              void* d_out, int out_size) {
    const float* x    = (const float*)d_in[0];
    const float* Wq   = (const float*)d_in[1];
    const float* Wk   = (const float*)d_in[2];
    const float* Wv   = (const float*)d_in[3];
    const float* Wo   = (const float*)d_in[4];
    const float* wln1 = (const float*)d_in[5];
    const float* wln2 = (const float*)d_in[6];
    const float* Wr   = (const float*)d_in[7];
    const float* Wg   = (const float*)d_in[8];
    const float* Wu   = (const float*)d_in[9];
    const float* Wd   = (const float*)d_in[10];
    float* out = (float*)d_out;

    float *p_hg, *p_rex, *p_wt;
    __half *p_q16, *p_k16, *p_vt16, *p_xn16, *p_ao16, *p_xn216, *p_hg16, *p_w16;
    int *p_tok, *p_cnt;
    cudaGetSymbolAddress((void**)&p_hg,    g_hg);
    cudaGetSymbolAddress((void**)&p_rex,   g_rex);
    cudaGetSymbolAddress((void**)&p_q16,   g_q16);
    cudaGetSymbolAddress((void**)&p_k16,   g_k16);
    cudaGetSymbolAddress((void**)&p_vt16,  g_vt16);
    cudaGetSymbolAddress((void**)&p_xn16,  g_xn16);
    cudaGetSymbolAddress((void**)&p_ao16,  g_ao16);
    cudaGetSymbolAddress((void**)&p_xn216, g_xn216);
    cudaGetSymbolAddress((void**)&p_hg16,  g_hg16);
    cudaGetSymbolAddress((void**)&p_w16,   g_w16);
    cudaGetSymbolAddress((void**)&p_tok,   g_tok);
    cudaGetSymbolAddress((void**)&p_wt,    g_wt);
    cudaGetSymbolAddress((void**)&p_cnt,   g_cnt);

    __half* p_P = (__half*)p_hg;                              // P aliased on g_hg
    __half* p_hgpre = (__half*)p_hg;                          // gate pre-act
    __half* p_hupre = (__half*)p_hg + (size_t)NE_ * T_ * I_;  // up pre-act

    static int smem_set = 0;
    if (!smem_set) {
        cudaFuncSetAttribute(hgemm, cudaFuncAttributeMaxDynamicSharedMemorySize, H_SMEM);
        cudaFuncSetAttribute(attn_score_h, cudaFuncAttributeMaxDynamicSharedMemorySize, H_SMEM);
        cudaFuncSetAttribute(attn_pv_h, cudaFuncAttributeMaxDynamicSharedMemorySize, H_SMEM);
        smem_set = 1;
    }

    zero_cnt_k<<<1, 32>>>();

    cvt16_k<<<2048, 256>>>(Wq, p_w16 + OFF_WQ, (size_t)H_ * H_ / 4);
    cvt16_k<<<2048, 256>>>(Wk, p_w16 + OFF_WK, (size_t)H_ * H_ / 4);
    cvt16_k<<<2048, 256>>>(Wv, p_w16 + OFF_WV, (size_t)H_ * H_ / 4);
    cvt16_k<<<2048, 256>>>(Wo, p_w16 + OFF_WO, (size_t)H_ * H_ / 4);
    cvt16_k<<<4096, 256>>>(Wg, p_w16 + OFF_WG, (size_t)NE_ * I_ * H_ / 4);
    cvt16_k<<<4096, 256>>>(Wu, p_w16 + OFF_WU, (size_t)NE_ * I_ * H_ / 4);
    cvt16_k<<<4096, 256>>>(Wd, p_w16 + OFF_WD, (size_t)NE_ * H_ * I_ / 4);

    rmsnorm_k<<<T_, 256>>>(x, wln1, p_xn16, nullptr);

    // QKV fused: q,k -> fp16 [t][H]; v -> fp16 transposed [b,h][d][s]
    {
        GArgs a = {};
        a.A = p_xn16;
        a.B0 = p_w16 + OFF_WQ; a.B1 = p_w16 + OFF_WK; a.B2 = p_w16 + OFF_WV;
        a.H0 = p_q16; a.H1 = p_k16; a.H2 = p_vt16;
        a.M = T_; a.N = H_; a.K = H_; a.lda = H_; a.ldb = H_; a.ldc = H_;
        a.mode = 0; a.qkv = 1;
        hgemm<<<dim3(H_ / 128, T_ / 128, 3), 256, H_SMEM>>>(a);
    }

    attn_score_h<<<dim3(S_ / 128, S_ / 128, B_ * NH_), 256, H_SMEM>>>(p_q16, p_k16);
    softmax_k<<<B_ * NH_ * S_, 256>>>(p_P);
    attn_pv_h<<<dim3(S_ / 128, B_ * NH_), 256, H_SMEM>>>(p_P, p_vt16, p_ao16);

    // Wo projection + fused residual (fp32 out)
    {
        GArgs a = {};
        a.A = p_ao16; a.B0 = p_w16 + OFF_WO; a.C0 = out;
        a.resid = x;
        a.M = T_; a.N = H_; a.K = H_; a.lda = H_; a.ldb = H_; a.ldc = H_;
        a.mode = 0;
        hgemm<<<dim3(H_ / 128, T_ / 128, 1), 256, H_SMEM>>>(a);
    }

    rmsnorm_k<<<T_, 256>>>(out, wln2, p_xn216, p_rex);
    router_k<<<T_ / 8, 256>>>(p_rex, Wr);

    // MoE gate+up (gathered A; fp16 pre-act outputs)
    {
        GArgs a = {};
        a.A = p_xn216;
        a.B0 = p_w16 + OFF_WG; a.B1 = p_w16 + OFF_WU;
        a.H0 = p_hgpre; a.H1 = p_hupre;
        a.M = T_; a.N = I_; a.K = H_; a.lda = H_; a.ldb = H_; a.ldc = I_;
        a.tok = p_tok; a.cntp = p_cnt;
        a.bStride = (size_t)I_ * H_; a.cStride = (size_t)T_ * I_;
        a.mode = 1;
        hgemm<<<dim3(I_ / 128, T_ / 128, 2 * NE_), 256, H_SMEM>>>(a);
    }

    swiglu_all_k<<<dim3(512, NE_), 256>>>(p_hgpre, p_hupre, p_hg16);

    // MoE down: atomic scatter-add into out
    {
        GArgs a = {};
        a.A = p_hg16; a.B0 = p_w16 + OFF_WD; a.C0 = out;
        a.M = T_; a.N = H_; a.K = I_; a.lda = I_; a.ldb = I_; a.ldc = H_;
        a.tok = p_tok; a.wt = p_wt; a.cntp = p_cnt;
        a.aStride = (size_t)T_ * I_; a.bStride = (size_t)H_ * I_;
        a.mode = 2;
        hgemm<<<dim3(H_ / 128, T_ / 128, NE_), 256, H_SMEM>>>(a);
    }
}

// round 11
// speedup vs baseline: 1.7938x; 1.0611x over previous
#include <cuda_runtime.h>
#include <cuda_fp16.h>
#include <math.h>
#include <stdint.h>

#define B_   2
#define S_   2048
#define H_   2048
#define NH_  16
#define HD_  128
#define NE_  8
#define I_   4096
#define T_   (B_*S_)
#define EPS_ 1e-5f
#define ATT_SCALE 0.08838834764831845f

// -------------------- scratch --------------------
__device__ float  g_att[(size_t)B_*NH_*S_*S_];     // fp32 scores
__device__ float  g_hg [(size_t)NE_*T_*I_];        // aliased: P(half) during attn; gate/up pre-act (2x half) in MoE
__device__ float  g_rex[(size_t)T_*H_];            // ln2 exact (router)
__device__ __half g_q16  [(size_t)T_*H_];
__device__ __half g_k16  [(size_t)T_*H_];
__device__ __half g_vt16 [(size_t)B_*NH_*HD_*S_];  // V transposed: [b,h][d][s]
__device__ __half g_xn16 [(size_t)T_*H_];
__device__ __half g_ao16 [(size_t)T_*H_];
__device__ __half g_xn216[(size_t)T_*H_];
__device__ __half g_hg16 [(size_t)NE_*T_*I_];      // swiglu out (down A)
#define OFF_WQ ((size_t)0)
#define OFF_WK ((size_t)H_*H_)
#define OFF_WV ((size_t)2*H_*H_)
#define OFF_WO ((size_t)3*H_*H_)
#define OFF_WG ((size_t)4*H_*H_)
#define OFF_WU (OFF_WG + (size_t)NE_*I_*H_)
#define OFF_WD (OFF_WU + (size_t)NE_*I_*H_)
#define W16_TOTAL (OFF_WD + (size_t)NE_*H_*I_)
__device__ __half g_w16[W16_TOTAL];
__device__ int   g_tok[NE_*T_];
__device__ float g_wt [NE_*T_];
__device__ int   g_cnt[NE_];

// -------------------- helpers --------------------
__device__ __forceinline__ void mma16h(float* c, const uint32_t* a, uint32_t b0, uint32_t b1) {
    asm volatile("mma.sync.aligned.m16n8k16.row.col.f32.f16.f16.f32 "
        "{%0,%1,%2,%3},{%4,%5,%6,%7},{%8,%9},{%0,%1,%2,%3};"
        : "+f"(c[0]), "+f"(c[1]), "+f"(c[2]), "+f"(c[3])
        : "r"(a[0]), "r"(a[1]), "r"(a[2]), "r"(a[3]), "r"(b0), "r"(b1));
}
__device__ __forceinline__ void ldsm4(uint32_t* r, uint32_t addr) {
    asm volatile("ldmatrix.sync.aligned.m8n8.x4.shared.b16 {%0,%1,%2,%3},[%4];"
        : "=r"(r[0]), "=r"(r[1]), "=r"(r[2]), "=r"(r[3]) : "r"(addr));
}
__device__ __forceinline__ void cpa16(uint32_t dst, const void* src) {
    asm volatile("cp.async.cg.shared.global [%0], [%1], 16;" :: "r"(dst), "l"(src));
}
__device__ __forceinline__ void cpa_commit() { asm volatile("cp.async.commit_group;"); }
__device__ __forceinline__ void cpa_wait1()  { asm volatile("cp.async.wait_group 1;" ::: "memory"); }
__device__ __forceinline__ uint32_t smem_u32(const void* p) {
    uint32_t a; asm("{ .reg .u64 t; cvta.to.shared.u64 t, %1; cvt.u32.u64 %0, t; }"
                    : "=r"(a) : "l"(p));
    return a;
}

#define HROWB 80
#define H_STG 3
#define H_STAGE (128*HROWB)
#define H_SMEM (2*H_STG*H_STAGE)      // 61440 B

// -------------------- small kernels --------------------
__global__ void zero_cnt_k() { if (threadIdx.x < NE_) g_cnt[threadIdx.x] = 0; }

// fp32 -> fp16: 8 floats per thread, one 16B packed store (LSU-friendly)
__global__ void cvt16_k(const float* __restrict__ s, __half* __restrict__ d, size_t n8) {
    size_t stride = (size_t)gridDim.x * blockDim.x;
    const float4* S = (const float4*)s;
    uint4* D = (uint4*)d;
    for (size_t i = (size_t)blockIdx.x * blockDim.x + threadIdx.x; i < n8; i += stride) {
        float4 v0 = S[2 * i], v1 = S[2 * i + 1];
        __half2 h0 = __floats2half2_rn(v0.x, v0.y);
        __half2 h1 = __floats2half2_rn(v0.z, v0.w);
        __half2 h2 = __floats2half2_rn(v1.x, v1.y);
        __half2 h3 = __floats2half2_rn(v1.z, v1.w);
        uint4 o;
        o.x = *(const uint32_t*)&h0;
        o.y = *(const uint32_t*)&h1;
        o.z = *(const uint32_t*)&h2;
        o.w = *(const uint32_t*)&h3;
        D[i] = o;
    }
}

__global__ void rmsnorm_k(const float* __restrict__ x, const float* __restrict__ w,
                          __half* __restrict__ o16, float* __restrict__ o_exact) {
    int t = blockIdx.x;
    const float* xr = x + (size_t)t * H_;
    float s = 0.f;
    for (int j = threadIdx.x; j < H_; j += blockDim.x) { float v = xr[j]; s += v * v; }
    __shared__ float red[32];
    for (int off = 16; off; off >>= 1) s += __shfl_xor_sync(0xffffffffu, s, off);
    if ((threadIdx.x & 31) == 0) red[threadIdx.x >> 5] = s;
    __syncthreads();
    if (threadIdx.x < 32) {
        float v = (threadIdx.x < (blockDim.x >> 5)) ? red[threadIdx.x] : 0.f;
        for (int off = 16; off; off >>= 1) v += __shfl_xor_sync(0xffffffffu, v, off);
        if (threadIdx.x == 0) red[0] = v;
    }
    __syncthreads();
    float inv = rsqrtf(red[0] / (float)H_ + EPS_);
    __half* orow = o16 + (size_t)t * H_;
    if (o_exact) {
        float* erow = o_exact + (size_t)t * H_;
        for (int j = threadIdx.x; j < H_; j += blockDim.x) {
            float v = xr[j] * inv * w[j];
            erow[j] = v;
            orow[j] = __float2half_rn(v);
        }
    } else {
        for (int j = threadIdx.x; j < H_; j += blockDim.x)
            orow[j] = __float2half_rn(xr[j] * inv * w[j]);
    }
}

// swiglu: fp16 pre-acts in, fp16 out
__global__ void swiglu_all_k(const __half* __restrict__ hgp, const __half* __restrict__ hup,
                             __half* __restrict__ ho) {
    int e = blockIdx.y;
    int cnt = g_cnt[e];
    const __half2* G = (const __half2*)(hgp + (size_t)e * T_ * I_);
    const __half2* U = (const __half2*)(hup + (size_t)e * T_ * I_);
    __half2* O = (__half2*)(ho + (size_t)e * T_ * I_);
    size_t total = (size_t)cnt * (I_ / 2);
    size_t stride = (size_t)gridDim.x * blockDim.x;
    for (size_t i = (size_t)blockIdx.x * blockDim.x + threadIdx.x; i < total; i += stride) {
        float2 g = __half22float2(G[i]);
        float2 u = __half22float2(U[i]);
        float a = g.x / (1.f + __expf(-g.x)) * u.x;
        float b = g.y / (1.f + __expf(-g.y)) * u.y;
        O[i] = __floats2half2_rn(a, b);
    }
}

// ==================== fp16 MMA GEMM ====================
// Mode 0 + qkv: z in {0,1}: half out to H0/H1; z==2: V transposed into H2 [b,h][d][s].
// Mode 0 (no qkv): fp32 out C0, optional resid.
// Mode 1: z = expert*2+{gate,up}; gathered A; half out to H0/H1 (+e*cStride).
// Mode 2: z = expert; dense per-expert A; atomic fp32 scatter-add.
struct GArgs {
    const __half* A;
    const __half* B0; const __half* B1; const __half* B2;
    float* C0;
    __half* H0; __half* H1; __half* H2;
    const float* resid;
    int M, N, K, lda, ldb, ldc;
    const int* tok; const float* wt; const int* cntp;
    size_t aStride, bStride, cStride;
    int mode;
    int qkv;
};

__global__ void __launch_bounds__(256, 2)
hgemm(const GArgs args) {
    int z = blockIdx.z;
    const __half* A = args.A;
    const __half* B;
    const int* a_idx = nullptr; const int* c_idx = nullptr; const float* c_w = nullptr;
    int cnt = args.M;
    int ep_mode;          // 0=fp32 (resid opt), 1=half H, 2=vtrans, 3=atomic
    float* Cf = args.C0;
    __half* Ch = nullptr;

    if (args.mode == 0) {
        B = (z == 0) ? args.B0 : (z == 1 ? args.B1 : args.B2);
        if (args.qkv) {
            if (z < 2) { Ch = z ? args.H1 : args.H0; ep_mode = 1; }
            else ep_mode = 2;
        } else ep_mode = 0;
    } else if (args.mode == 1) {
        int e = z >> 1;
        B = ((z & 1) ? args.B1 : args.B0) + (size_t)e * args.bStride;
        Ch = ((z & 1) ? args.H1 : args.H0) + (size_t)e * args.cStride;
        a_idx = args.tok + e * T_;
        cnt = args.cntp[e];
        ep_mode = 1;
    } else {
        int e = z;
        A = args.A + (size_t)e * args.aStride;
        B = args.B0 + (size_t)e * args.bStride;
        c_idx = args.tok + e * T_;
        c_w = args.wt + e * T_;
        cnt = args.cntp[e];
        ep_mode = 3;
    }

    int m0 = blockIdx.y * 128, n0 = blockIdx.x * 128;
    if (m0 >= cnt) return;

    extern __shared__ char smem[];
    uint32_t sA = smem_u32(smem);
    uint32_t sB = sA + H_STG * H_STAGE;

    int tid = threadIdx.x;
    int lane = tid & 31, w = tid >> 5;
    int wm = (w & 3) * 32, wn = (w >> 2) * 64;

    int lrow = tid >> 2;
    int lch  = tid & 3;
    const __half* gA[2]; const __half* gB[2];
    uint32_t stA[2], stB[2];
#pragma unroll
    for (int rr = 0; rr < 2; rr++) {
        int r = lrow + rr * 64;
        int mr = m0 + r;
        int grow = a_idx ? ((mr < cnt) ? a_idx[mr] : 0) : mr;
        gA[rr] = A + (size_t)grow * args.lda + lch * 8;
        gB[rr] = B + (size_t)(n0 + r) * args.ldb + lch * 8;
        stA[rr] = sA + r * HROWB + lch * 16;
        stB[rr] = sB + r * HROWB + lch * 16;
    }

    uint32_t aAddr = sA + (wm + (lane & 15)) * HROWB + ((lane >> 4) & 1) * 16;
    uint32_t bAddr = sB + (wn + (lane & 7) + 8 * ((lane >> 4) & 1)) * HROWB
                        + ((lane >> 3) & 1) * 16;

    float acc[2][8][4];
#pragma unroll
    for (int i = 0; i < 2; i++)
#pragma unroll
        for (int j = 0; j < 8; j++)
#pragma unroll
            for (int q = 0; q < 4; q++) acc[i][j][q] = 0.f;

    int nk = args.K / 32;

#pragma unroll
    for (int s = 0; s < 2; s++) {
#pragma unroll
        for (int rr = 0; rr < 2; rr++) {
            cpa16(stA[rr] + s * H_STAGE, gA[rr] + s * 32);
            cpa16(stB[rr] + s * H_STAGE, gB[rr] + s * 32);
        }
        cpa_commit();
    }

    for (int kt = 0; kt < nk; kt++) {
        cpa_wait1();
        __syncthreads();      // publishes stage kt%3; also fences last iter's readers of stage (kt+2)%3
        if (kt + 2 < nk) {
            int kb = (kt + 2) * 32;
            uint32_t off = ((kt + 2) % H_STG) * H_STAGE;
#pragma unroll
            for (int rr = 0; rr < 2; rr++) {
                cpa16(stA[rr] + off, gA[rr] + kb);
                cpa16(stB[rr] + off, gB[rr] + kb);
            }
        }
        cpa_commit();

        uint32_t soff = (kt % H_STG) * H_STAGE;
#pragma unroll
        for (int ks = 0; ks < 2; ks++) {
            uint32_t koff = soff + ks * 32;
            uint32_t a[2][4];
            ldsm4(a[0], aAddr + koff);
            ldsm4(a[1], aAddr + koff + 16 * HROWB);
            uint32_t b[4][4];
#pragma unroll
            for (int jp = 0; jp < 4; jp++)
                ldsm4(b[jp], bAddr + koff + jp * (16 * HROWB));
#pragma unroll
            for (int im = 0; im < 2; im++)
#pragma unroll
                for (int jn = 0; jn < 8; jn++)
                    mma16h(acc[im][jn], a[im], b[jn >> 1][(jn & 1) * 2], b[jn >> 1][(jn & 1) * 2 + 1]);
        }
        // no trailing sync: 3-stage buffering makes the leading barrier sufficient
    }

    int cg = 2 * (lane & 3);
#pragma unroll
    for (int im = 0; im < 2; im++) {
#pragma unroll
        for (int half = 0; half < 2; half++) {
            int m = m0 + wm + im * 16 + (lane >> 2) + half * 8;
            if (m >= cnt) continue;
            if (ep_mode == 3) {
                int tr = c_idx[m]; float wv = c_w[m];
                float* cp = Cf + (size_t)tr * args.ldc + n0 + wn + cg;
#pragma unroll
                for (int jn = 0; jn < 8; jn++) {
                    atomicAdd(cp + jn * 8,     wv * acc[im][jn][half * 2 + 0]);
                    atomicAdd(cp + jn * 8 + 1, wv * acc[im][jn][half * 2 + 1]);
                }
            } else if (ep_mode == 1) {
                __half* cp = Ch + (size_t)m * args.ldc + n0 + wn + cg;
#pragma unroll
                for (int jn = 0; jn < 8; jn++)
                    *((__half2*)(cp + jn * 8)) =
                        __floats2half2_rn(acc[im][jn][half * 2 + 0], acc[im][jn][half * 2 + 1]);
            } else if (ep_mode == 2) {
                int bb = m >> 11, ss = m & (S_ - 1);
#pragma unroll
                for (int jn = 0; jn < 8; jn++) {
                    int col = n0 + wn + cg + jn * 8;
                    int hh = col >> 7, d = col & 127;
                    size_t base = ((size_t)(bb * NH_ + hh) * HD_ + d) * S_ + ss;
                    args.H2[base]      = __float2half_rn(acc[im][jn][half * 2 + 0]);
                    args.H2[base + S_] = __float2half_rn(acc[im][jn][half * 2 + 1]);
                }
            } else {
                float* cp = Cf + (size_t)m * args.ldc + n0 + wn + cg;
                if (args.resid) {
                    const float* rp = args.resid + (size_t)m * args.ldc + n0 + wn + cg;
#pragma unroll
                    for (int jn = 0; jn < 8; jn++) {
                        float2 r = *((const float2*)(rp + jn * 8));
                        float2 o;
                        o.x = acc[im][jn][half * 2 + 0] + r.x;
                        o.y = acc[im][jn][half * 2 + 1] + r.y;
                        *((float2*)(cp + jn * 8)) = o;
                    }
                } else {
#pragma unroll
                    for (int jn = 0; jn < 8; jn++) {
                        float2 o;
                        o.x = acc[im][jn][half * 2 + 0];
                        o.y = acc[im][jn][half * 2 + 1];
                        *((float2*)(cp + jn * 8)) = o;
                    }
                }
            }
        }
    }
}

// ==================== causal scores (fp16 pipelined) ====================
__global__ void __launch_bounds__(256, 2)
attn_score_h(const __half* __restrict__ Q, const __half* __restrict__ K16) {
    int bh = blockIdx.z, b = bh >> 4, h = bh & 15;
    int m0 = blockIdx.y * 128, n0 = blockIdx.x * 128;
    if (n0 > m0) return;

    const __half* Qb = Q + (size_t)b * S_ * H_ + h * HD_;
    const __half* Kb = K16 + (size_t)b * S_ * H_ + h * HD_;
    float* Sb = g_att + (size_t)bh * S_ * S_;

    extern __shared__ char smem[];
    uint32_t sA = smem_u32(smem);
    uint32_t sB = sA + H_STG * H_STAGE;

    int tid = threadIdx.x;
    int lane = tid & 31, w = tid >> 5;
    int wm = (w & 3) * 32, wn = (w >> 2) * 64;

    int lrow = tid >> 2, lch = tid & 3;
    const __half* gA[2]; const __half* gB[2];
    uint32_t stA[2], stB[2];
#pragma unroll
    for (int rr = 0; rr < 2; rr++) {
        int r = lrow + rr * 64;
        gA[rr] = Qb + (size_t)(m0 + r) * H_ + lch * 8;
        gB[rr] = Kb + (size_t)(n0 + r) * H_ + lch * 8;
        stA[rr] = sA + r * HROWB + lch * 16;
        stB[rr] = sB + r * HROWB + lch * 16;
    }

    uint32_t aAddr = sA + (wm + (lane & 15)) * HROWB + ((lane >> 4) & 1) * 16;
    uint32_t bAddr = sB + (wn + (lane & 7) + 8 * ((lane >> 4) & 1)) * HROWB
                        + ((lane >> 3) & 1) * 16;

    float acc[2][8][4];
#pragma unroll
    for (int i = 0; i < 2; i++)
#pragma unroll
        for (int j = 0; j < 8; j++)
#pragma unroll
            for (int q = 0; q < 4; q++) acc[i][j][q] = 0.f;

    const int nk = HD_ / 32;   // 4

#pragma unroll
    for (int s = 0; s < 2; s++) {
#pragma unroll
        for (int rr = 0; rr < 2; rr++) {
            cpa16(stA[rr] + s * H_STAGE, gA[rr] + s * 32);
            cpa16(stB[rr] + s * H_STAGE, gB[rr] + s * 32);
        }
        cpa_commit();
    }

    for (int kt = 0; kt < nk; kt++) {
        cpa_wait1();
        __syncthreads();
        if (kt + 2 < nk) {
            int kb = (kt + 2) * 32;
            uint32_t off = ((kt + 2) % H_STG) * H_STAGE;
#pragma unroll
            for (int rr = 0; rr < 2; rr++) {
                cpa16(stA[rr] + off, gA[rr] + kb);
                cpa16(stB[rr] + off, gB[rr] + kb);
            }
        }
        cpa_commit();

        uint32_t soff = (kt % H_STG) * H_STAGE;
#pragma unroll
        for (int ks = 0; ks < 2; ks++) {
            uint32_t koff = soff + ks * 32;
            uint32_t a[2][4];
            ldsm4(a[0], aAddr + koff);
            ldsm4(a[1], aAddr + koff + 16 * HROWB);
            uint32_t b2[4][4];
#pragma unroll
            for (int jp = 0; jp < 4; jp++)
                ldsm4(b2[jp], bAddr + koff + jp * (16 * HROWB));
#pragma unroll
            for (int im = 0; im < 2; im++)
#pragma unroll
                for (int jn = 0; jn < 8; jn++)
                    mma16h(acc[im][jn], a[im], b2[jn >> 1][(jn & 1) * 2], b2[jn >> 1][(jn & 1) * 2 + 1]);
        }
        // no trailing sync (3-stage)
    }

    int cg = 2 * (lane & 3);
#pragma unroll
    for (int im = 0; im < 2; im++) {
#pragma unroll
        for (int half = 0; half < 2; half++) {
            int i = m0 + wm + im * 16 + (lane >> 2) + half * 8;
            float* cp = Sb + (size_t)i * S_ + n0 + wn + cg;
#pragma unroll
            for (int jn = 0; jn < 8; jn++) {
                int j = n0 + wn + cg + jn * 8;
                float2 o;
                o.x = (j     > i) ? -1e30f : acc[im][jn][half * 2 + 0] * ATT_SCALE;
                o.y = (j + 1 > i) ? -1e30f : acc[im][jn][half * 2 + 1] * ATT_SCALE;
                *((float2*)(cp + jn * 8)) = o;
            }
        }
    }
}

// ==================== adaptive row softmax: fp32 scores in, fp16 P out ====================
__global__ void softmax_k(__half* __restrict__ P) {
    int r = blockIdx.x & (S_ - 1);
    const float* row = g_att + (size_t)blockIdx.x * S_;
    __half* prow = P + (size_t)blockIdx.x * S_;
    int len = r + 1;
    int tid = threadIdx.x;
    float v[8];
    float mx = -1e30f;
#pragma unroll
    for (int i = 0; i < 8; i++) {
        int j = tid + i * 256;
        v[i] = (j < len) ? row[j] : -1e30f;
        mx = fmaxf(mx, v[i]);
    }
    __shared__ float red[32];
    for (int off = 16; off; off >>= 1) mx = fmaxf(mx, __shfl_xor_sync(0xffffffffu, mx, off));
    if ((tid & 31) == 0) red[tid >> 5] = mx;
    __syncthreads();
    if (tid < 32) {
        float m2 = (tid < 8) ? red[tid] : -1e38f;
        for (int off = 16; off; off >>= 1) m2 = fmaxf(m2, __shfl_xor_sync(0xffffffffu, m2, off));
        if (tid == 0) red[0] = m2;
    }
    __syncthreads();
    mx = red[0];
    float s = 0.f;
#pragma unroll
    for (int i = 0; i < 8; i++) { v[i] = __expf(v[i] - mx); s += v[i]; }
    __syncthreads();
    for (int off = 16; off; off >>= 1) s += __shfl_xor_sync(0xffffffffu, s, off);
    if ((tid & 31) == 0) red[tid >> 5] = s;
    __syncthreads();
    if (tid < 32) {
        float s2 = (tid < 8) ? red[tid] : 0.f;
        for (int off = 16; off; off >>= 1) s2 += __shfl_xor_sync(0xffffffffu, s2, off);
        if (tid == 0) red[0] = s2;
    }
    __syncthreads();
    float inv = 1.f / red[0];
#pragma unroll
    for (int i = 0; i < 8; i++) {
        int j = tid + i * 256;
        if (j < len) prow[j] = __float2half_rn(v[i] * inv);
    }
    int kmax = ((r >> 7) + 1) << 7;
    for (int j = len + tid; j < kmax; j += 256) prow[j] = __float2half_rn(0.f);
}

// ==================== P @ Vt (fp16 pipelined, causal-truncated) ====================
__global__ void __launch_bounds__(256, 2)
attn_pv_h(const __half* __restrict__ P, const __half* __restrict__ Vt,
          __half* __restrict__ O) {
    int bh = blockIdx.y, b = bh >> 4, h = bh & 15;
    int m0 = blockIdx.x * 128;
    const __half* Pb = P + (size_t)bh * S_ * S_;
    const __half* Vb = Vt + (size_t)bh * HD_ * S_;

    extern __shared__ char smem[];
    uint32_t sA = smem_u32(smem);
    uint32_t sB = sA + H_STG * H_STAGE;

    int tid = threadIdx.x;
    int lane = tid & 31, w = tid >> 5;
    int wm = (w & 3) * 32, wn = (w >> 2) * 64;

    int lrow = tid >> 2, lch = tid & 3;
    const __half* gA[2]; const __half* gB[2];
    uint32_t stA[2], stB[2];
#pragma unroll
    for (int rr = 0; rr < 2; rr++) {
        int r = lrow + rr * 64;
        gA[rr] = Pb + (size_t)(m0 + r) * S_ + lch * 8;
        gB[rr] = Vb + (size_t)r * S_ + lch * 8;     // B rows = d (128), K-major along s
        stA[rr] = sA + r * HROWB + lch * 16;
        stB[rr] = sB + r * HROWB + lch * 16;
    }

    uint32_t aAddr = sA + (wm + (lane & 15)) * HROWB + ((lane >> 4) & 1) * 16;
    uint32_t bAddr = sB + (wn + (lane & 7) + 8 * ((lane >> 4) & 1)) * HROWB
                        + ((lane >> 3) & 1) * 16;

    float acc[2][8][4];
#pragma unroll
    for (int i = 0; i < 2; i++)
#pragma unroll
        for (int j = 0; j < 8; j++)
#pragma unroll
            for (int q = 0; q < 4; q++) acc[i][j][q] = 0.f;

    int nk = (m0 + 128) / 32;

#pragma unroll
    for (int s = 0; s < 2; s++) {
#pragma unroll
        for (int rr = 0; rr < 2; rr++) {
            cpa16(stA[rr] + s * H_STAGE, gA[rr] + s * 32);
            cpa16(stB[rr] + s * H_STAGE, gB[rr] + s * 32);
        }
        cpa_commit();
    }

    for (int kt = 0; kt < nk; kt++) {
        cpa_wait1();
        __syncthreads();
        if (kt + 2 < nk) {
            int kb = (kt + 2) * 32;
            uint32_t off = ((kt + 2) % H_STG) * H_STAGE;
#pragma unroll
            for (int rr = 0; rr < 2; rr++) {
                cpa16(stA[rr] + off, gA[rr] + kb);
                cpa16(stB[rr] + off, gB[rr] + kb);
            }
        }
        cpa_commit();

        uint32_t soff = (kt % H_STG) * H_STAGE;
#pragma unroll
        for (int ks = 0; ks < 2; ks++) {
            uint32_t koff = soff + ks * 32;
            uint32_t a[2][4];
            ldsm4(a[0], aAddr + koff);
            ldsm4(a[1], aAddr + koff + 16 * HROWB);
            uint32_t b2[4][4];
#pragma unroll
            for (int jp = 0; jp < 4; jp++)
                ldsm4(b2[jp], bAddr + koff + jp * (16 * HROWB));
#pragma unroll
            for (int im = 0; im < 2; im++)
#pragma unroll
                for (int jn = 0; jn < 8; jn++)
                    mma16h(acc[im][jn], a[im], b2[jn >> 1][(jn & 1) * 2], b2[jn >> 1][(jn & 1) * 2 + 1]);
        }
        // no trailing sync (3-stage)
    }

    int cg = 2 * (lane & 3);
#pragma unroll
    for (int im = 0; im < 2; im++) {
#pragma unroll
        for (int half = 0; half < 2; half++) {
            int m = m0 + wm + im * 16 + (lane >> 2) + half * 8;
            __half* cp = O + (size_t)(b * S_ + m) * H_ + h * HD_ + wn + cg;
#pragma unroll
            for (int jn = 0; jn < 8; jn++)
                *((__half2*)(cp + jn * 8)) =
                    __floats2half2_rn(acc[im][jn][half * 2 + 0], acc[im][jn][half * 2 + 1]);
        }
    }
}

// ==================== router (EXACT fp32 input) ====================
__global__ void router_k(const float* __restrict__ xn2e, const float* __restrict__ Wr) {
    int t = blockIdx.x * (blockDim.x >> 5) + (threadIdx.x >> 5);
    if (t >= T_) return;
    int lane = threadIdx.x & 31;
    const float* xr = xn2e + (size_t)t * H_;
    float s[NE_];
#pragma unroll
    for (int e = 0; e < NE_; e++) s[e] = 0.f;
    for (int j = lane; j < H_; j += 32) {
        float xv = xr[j];
#pragma unroll
        for (int e = 0; e < NE_; e++) s[e] += xv * Wr[e * H_ + j];
    }
#pragma unroll
    for (int e = 0; e < NE_; e++)
        for (int off = 16; off; off >>= 1) s[e] += __shfl_xor_sync(0xffffffffu, s[e], off);
    if (lane == 0) {
        int b0 = 0;
#pragma unroll
        for (int e = 1; e < NE_; e++) if (s[e] > s[b0]) b0 = e;
        int b1 = -1;
#pragma unroll
        for (int e = 0; e < NE_; e++) {
            if (e == b0) continue;
            if (b1 < 0 || s[e] > s[b1]) b1 = e;
        }
        float m = s[b0];
        float e0 = __expf(s[b0] - m), e1 = __expf(s[b1] - m);
        float inv = 1.f / (e0 + e1);
        int pos = atomicAdd(&g_cnt[b0], 1);
        g_tok[b0 * T_ + pos] = t; g_wt[b0 * T_ + pos] = e0 * inv;
        pos = atomicAdd(&g_cnt[b1], 1);
        g_tok[b1 * T_ + pos] = t; g_wt[b1 * T_ + pos] = e1 * inv;
    }
}

// ==================== host ====================
extern "C" void kernel_launch(void* const* d_in, const int* in_sizes, int n_in,
                              void* d_out, int out_size) {
    const float* x    = (const float*)d_in[0];
    const float* Wq   = (const float*)d_in[1];
    const float* Wk   = (const float*)d_in[2];
    const float* Wv   = (const float*)d_in[3];
    const float* Wo   = (const float*)d_in[4];
    const float* wln1 = (const float*)d_in[5];
    const float* wln2 = (const float*)d_in[6];
    const float* Wr   = (const float*)d_in[7];
    const float* Wg   = (const float*)d_in[8];
    const float* Wu   = (const float*)d_in[9];
    const float* Wd   = (const float*)d_in[10];
    float* out = (float*)d_out;

    float *p_hg, *p_rex, *p_wt;
    __half *p_q16, *p_k16, *p_vt16, *p_xn16, *p_ao16, *p_xn216, *p_hg16, *p_w16;
    int *p_tok, *p_cnt;
    cudaGetSymbolAddress((void**)&p_hg,    g_hg);
    cudaGetSymbolAddress((void**)&p_rex,   g_rex);
    cudaGetSymbolAddress((void**)&p_q16,   g_q16);
    cudaGetSymbolAddress((void**)&p_k16,   g_k16);
    cudaGetSymbolAddress((void**)&p_vt16,  g_vt16);
    cudaGetSymbolAddress((void**)&p_xn16,  g_xn16);
    cudaGetSymbolAddress((void**)&p_ao16,  g_ao16);
    cudaGetSymbolAddress((void**)&p_xn216, g_xn216);
    cudaGetSymbolAddress((void**)&p_hg16,  g_hg16);
    cudaGetSymbolAddress((void**)&p_w16,   g_w16);
    cudaGetSymbolAddress((void**)&p_tok,   g_tok);
    cudaGetSymbolAddress((void**)&p_wt,    g_wt);
    cudaGetSymbolAddress((void**)&p_cnt,   g_cnt);

    __half* p_P = (__half*)p_hg;                              // P aliased on g_hg
    __half* p_hgpre = (__half*)p_hg;                          // gate pre-act
    __half* p_hupre = (__half*)p_hg + (size_t)NE_ * T_ * I_;  // up pre-act

    static int smem_set = 0;
    if (!smem_set) {
        cudaFuncSetAttribute(hgemm, cudaFuncAttributeMaxDynamicSharedMemorySize, H_SMEM);
        cudaFuncSetAttribute(attn_score_h, cudaFuncAttributeMaxDynamicSharedMemorySize, H_SMEM);
        cudaFuncSetAttribute(attn_pv_h, cudaFuncAttributeMaxDynamicSharedMemorySize, H_SMEM);
        smem_set = 1;
    }

    zero_cnt_k<<<1, 32>>>();

    cvt16_k<<<1024, 256>>>(Wq, p_w16 + OFF_WQ, (size_t)H_ * H_ / 8);
    cvt16_k<<<1024, 256>>>(Wk, p_w16 + OFF_WK, (size_t)H_ * H_ / 8);
    cvt16_k<<<1024, 256>>>(Wv, p_w16 + OFF_WV, (size_t)H_ * H_ / 8);
    cvt16_k<<<1024, 256>>>(Wo, p_w16 + OFF_WO, (size_t)H_ * H_ / 8);
    cvt16_k<<<4096, 256>>>(Wg, p_w16 + OFF_WG, (size_t)NE_ * I_ * H_ / 8);
    cvt16_k<<<4096, 256>>>(Wu, p_w16 + OFF_WU, (size_t)NE_ * I_ * H_ / 8);
    cvt16_k<<<4096, 256>>>(Wd, p_w16 + OFF_WD, (size_t)NE_ * H_ * I_ / 8);

    rmsnorm_k<<<T_, 256>>>(x, wln1, p_xn16, nullptr);

    // QKV fused: q,k -> fp16 [t][H]; v -> fp16 transposed [b,h][d][s]
    {
        GArgs a = {};
        a.A = p_xn16;
        a.B0 = p_w16 + OFF_WQ; a.B1 = p_w16 + OFF_WK; a.B2 = p_w16 + OFF_WV;
        a.H0 = p_q16; a.H1 = p_k16; a.H2 = p_vt16;
        a.M = T_; a.N = H_; a.K = H_; a.lda = H_; a.ldb = H_; a.ldc = H_;
        a.mode = 0; a.qkv = 1;
        hgemm<<<dim3(H_ / 128, T_ / 128, 3), 256, H_SMEM>>>(a);
    }

    attn_score_h<<<dim3(S_ / 128, S_ / 128, B_ * NH_), 256, H_SMEM>>>(p_q16, p_k16);
    softmax_k<<<B_ * NH_ * S_, 256>>>(p_P);
    attn_pv_h<<<dim3(S_ / 128, B_ * NH_), 256, H_SMEM>>>(p_P, p_vt16, p_ao16);

    // Wo projection + fused residual (fp32 out)
    {
        GArgs a = {};
        a.A = p_ao16; a.B0 = p_w16 + OFF_WO; a.C0 = out;
        a.resid = x;
        a.M = T_; a.N = H_; a.K = H_; a.lda = H_; a.ldb = H_; a.ldc = H_;
        a.mode = 0;
        hgemm<<<dim3(H_ / 128, T_ / 128, 1), 256, H_SMEM>>>(a);
    }

    rmsnorm_k<<<T_, 256>>>(out, wln2, p_xn216, p_rex);
    router_k<<<T_ / 8, 256>>>(p_rex, Wr);

    // MoE gate+up (gathered A; fp16 pre-act outputs)
    {
        GArgs a = {};
        a.A = p_xn216;
        a.B0 = p_w16 + OFF_WG; a.B1 = p_w16 + OFF_WU;
        a.H0 = p_hgpre; a.H1 = p_hupre;
        a.M = T_; a.N = I_; a.K = H_; a.lda = H_; a.ldb = H_; a.ldc = I_;
        a.tok = p_tok; a.cntp = p_cnt;
        a.bStride = (size_t)I_ * H_; a.cStride = (size_t)T_ * I_;
        a.mode = 1;
        hgemm<<<dim3(I_ / 128, T_ / 128, 2 * NE_), 256, H_SMEM>>>(a);
    }

    swiglu_all_k<<<dim3(512, NE_), 256>>>(p_hgpre, p_hupre, p_hg16);

    // MoE down: atomic scatter-add into out
    {
        GArgs a = {};
        a.A = p_hg16; a.B0 = p_w16 + OFF_WD; a.C0 = out;
        a.M = T_; a.N = H_; a.K = I_; a.lda = I_; a.ldb = I_; a.ldc = H_;
        a.tok = p_tok; a.wt = p_wt; a.cntp = p_cnt;
        a.aStride = (size_t)T_ * I_; a.bStride = (size_t)H_ * I_;
        a.mode = 2;
        hgemm<<<dim3(H_ / 128, T_ / 128, NE_), 256, H_SMEM>>>(a);
    }
}

// round 12
// speedup vs baseline: 1.8501x; 1.0314x over previous
#include <cuda_runtime.h>
#include <cuda_fp16.h>
#include <math.h>
#include <stdint.h>

#define B_   2
#define S_   2048
#define H_   2048
#define NH_  16
#define HD_  128
#define NE_  8
#define I_   4096
#define T_   (B_*S_)
#define EPS_ 1e-5f
#define ATT_SCALE 0.08838834764831845f

// -------------------- scratch --------------------
__device__ float  g_att[(size_t)B_*NH_*S_*S_];     // fp32 scores
__device__ float  g_hg [(size_t)NE_*T_*I_];        // aliased: P(half) during attn; gate/up pre-act (2x half) in MoE
__device__ float  g_rex[(size_t)T_*H_];            // ln2 exact (router)
__device__ __half g_q16  [(size_t)T_*H_];
__device__ __half g_k16  [(size_t)T_*H_];
__device__ __half g_vt16 [(size_t)B_*NH_*HD_*S_];  // V transposed: [b,h][d][s]
__device__ __half g_xn16 [(size_t)T_*H_];
__device__ __half g_ao16 [(size_t)T_*H_];
__device__ __half g_xn216[(size_t)T_*H_];
__device__ __half g_hg16 [(size_t)NE_*T_*I_];      // swiglu out (down A)
#define OFF_WQ ((size_t)0)
#define OFF_WK ((size_t)H_*H_)
#define OFF_WV ((size_t)2*H_*H_)
#define OFF_WO ((size_t)3*H_*H_)
#define OFF_WG ((size_t)4*H_*H_)
#define OFF_WU (OFF_WG + (size_t)NE_*I_*H_)
#define OFF_WD (OFF_WU + (size_t)NE_*I_*H_)
#define W16_TOTAL (OFF_WD + (size_t)NE_*H_*I_)
__device__ __half g_w16[W16_TOTAL];
__device__ int   g_tok[NE_*T_];
__device__ float g_wt [NE_*T_];
__device__ int   g_cnt[NE_];

// -------------------- helpers --------------------
__device__ __forceinline__ void mma16h(float* c, const uint32_t* a, uint32_t b0, uint32_t b1) {
    asm volatile("mma.sync.aligned.m16n8k16.row.col.f32.f16.f16.f32 "
        "{%0,%1,%2,%3},{%4,%5,%6,%7},{%8,%9},{%0,%1,%2,%3};"
        : "+f"(c[0]), "+f"(c[1]), "+f"(c[2]), "+f"(c[3])
        : "r"(a[0]), "r"(a[1]), "r"(a[2]), "r"(a[3]), "r"(b0), "r"(b1));
}
__device__ __forceinline__ void ldsm4(uint32_t* r, uint32_t addr) {
    asm volatile("ldmatrix.sync.aligned.m8n8.x4.shared.b16 {%0,%1,%2,%3},[%4];"
        : "=r"(r[0]), "=r"(r[1]), "=r"(r[2]), "=r"(r[3]) : "r"(addr));
}
__device__ __forceinline__ void cpa16(uint32_t dst, const void* src) {
    asm volatile("cp.async.cg.shared.global [%0], [%1], 16;" :: "r"(dst), "l"(src));
}
__device__ __forceinline__ void cpa_commit() { asm volatile("cp.async.commit_group;"); }
__device__ __forceinline__ void cpa_wait1()  { asm volatile("cp.async.wait_group 1;" ::: "memory"); }
__device__ __forceinline__ uint32_t smem_u32(const void* p) {
    uint32_t a; asm("{ .reg .u64 t; cvta.to.shared.u64 t, %1; cvt.u32.u64 %0, t; }"
                    : "=r"(a) : "l"(p));
    return a;
}

#define HROWB 80
#define H_STG 3
#define H_STAGE (128*HROWB)
#define H_SMEM (2*H_STG*H_STAGE)      // 61440 B

// -------------------- small kernels --------------------
__global__ void zero_cnt_k() { if (threadIdx.x < NE_) g_cnt[threadIdx.x] = 0; }

// fp32 -> fp16: 8 floats per thread, one 16B packed store
__global__ void cvt16_k(const float* __restrict__ s, __half* __restrict__ d, size_t n8) {
    size_t stride = (size_t)gridDim.x * blockDim.x;
    const float4* S = (const float4*)s;
    uint4* D = (uint4*)d;
    for (size_t i = (size_t)blockIdx.x * blockDim.x + threadIdx.x; i < n8; i += stride) {
        float4 v0 = S[2 * i], v1 = S[2 * i + 1];
        __half2 h0 = __floats2half2_rn(v0.x, v0.y);
        __half2 h1 = __floats2half2_rn(v0.z, v0.w);
        __half2 h2 = __floats2half2_rn(v1.x, v1.y);
        __half2 h3 = __floats2half2_rn(v1.z, v1.w);
        uint4 o;
        o.x = *(const uint32_t*)&h0;
        o.y = *(const uint32_t*)&h1;
        o.z = *(const uint32_t*)&h2;
        o.w = *(const uint32_t*)&h3;
        D[i] = o;
    }
}

__global__ void rmsnorm_k(const float* __restrict__ x, const float* __restrict__ w,
                          __half* __restrict__ o16, float* __restrict__ o_exact) {
    int t = blockIdx.x;
    const float* xr = x + (size_t)t * H_;
    float s = 0.f;
    for (int j = threadIdx.x; j < H_; j += blockDim.x) { float v = xr[j]; s += v * v; }
    __shared__ float red[32];
    for (int off = 16; off; off >>= 1) s += __shfl_xor_sync(0xffffffffu, s, off);
    if ((threadIdx.x & 31) == 0) red[threadIdx.x >> 5] = s;
    __syncthreads();
    if (threadIdx.x < 32) {
        float v = (threadIdx.x < (blockDim.x >> 5)) ? red[threadIdx.x] : 0.f;
        for (int off = 16; off; off >>= 1) v += __shfl_xor_sync(0xffffffffu, v, off);
        if (threadIdx.x == 0) red[0] = v;
    }
    __syncthreads();
    float inv = rsqrtf(red[0] / (float)H_ + EPS_);
    __half* orow = o16 + (size_t)t * H_;
    if (o_exact) {
        float* erow = o_exact + (size_t)t * H_;
        for (int j = threadIdx.x; j < H_; j += blockDim.x) {
            float v = xr[j] * inv * w[j];
            erow[j] = v;
            orow[j] = __float2half_rn(v);
        }
    } else {
        for (int j = threadIdx.x; j < H_; j += blockDim.x)
            orow[j] = __float2half_rn(xr[j] * inv * w[j]);
    }
}

// swiglu: fp16 pre-acts in, fp16 out
__global__ void swiglu_all_k(const __half* __restrict__ hgp, const __half* __restrict__ hup,
                             __half* __restrict__ ho) {
    int e = blockIdx.y;
    int cnt = g_cnt[e];
    const __half2* G = (const __half2*)(hgp + (size_t)e * T_ * I_);
    const __half2* U = (const __half2*)(hup + (size_t)e * T_ * I_);
    __half2* O = (__half2*)(ho + (size_t)e * T_ * I_);
    size_t total = (size_t)cnt * (I_ / 2);
    size_t stride = (size_t)gridDim.x * blockDim.x;
    for (size_t i = (size_t)blockIdx.x * blockDim.x + threadIdx.x; i < total; i += stride) {
        float2 g = __half22float2(G[i]);
        float2 u = __half22float2(U[i]);
        float a = g.x / (1.f + __expf(-g.x)) * u.x;
        float b = g.y / (1.f + __expf(-g.y)) * u.y;
        O[i] = __floats2half2_rn(a, b);
    }
}

// ==================== fp16 MMA GEMM ====================
struct GArgs {
    const __half* A;
    const __half* B0; const __half* B1; const __half* B2;
    float* C0;
    __half* H0; __half* H1; __half* H2;
    const float* resid;
    int M, N, K, lda, ldb, ldc;
    const int* tok; const float* wt; const int* cntp;
    size_t aStride, bStride, cStride;
    int mode;
    int qkv;
};

__global__ void __launch_bounds__(256, 2)
hgemm(const GArgs args) {
    int z = blockIdx.z;
    const __half* A = args.A;
    const __half* B;
    const int* a_idx = nullptr; const int* c_idx = nullptr; const float* c_w = nullptr;
    int cnt = args.M;
    int ep_mode;          // 0=fp32 (resid opt), 1=half H, 2=vtrans, 3=atomic
    float* Cf = args.C0;
    __half* Ch = nullptr;

    if (args.mode == 0) {
        B = (z == 0) ? args.B0 : (z == 1 ? args.B1 : args.B2);
        if (args.qkv) {
            if (z < 2) { Ch = z ? args.H1 : args.H0; ep_mode = 1; }
            else ep_mode = 2;
        } else ep_mode = 0;
    } else if (args.mode == 1) {
        int e = z >> 1;
        B = ((z & 1) ? args.B1 : args.B0) + (size_t)e * args.bStride;
        Ch = ((z & 1) ? args.H1 : args.H0) + (size_t)e * args.cStride;
        a_idx = args.tok + e * T_;
        cnt = args.cntp[e];
        ep_mode = 1;
    } else {
        int e = z;
        A = args.A + (size_t)e * args.aStride;
        B = args.B0 + (size_t)e * args.bStride;
        c_idx = args.tok + e * T_;
        c_w = args.wt + e * T_;
        cnt = args.cntp[e];
        ep_mode = 3;
    }

    int m0 = blockIdx.y * 128, n0 = blockIdx.x * 128;
    if (m0 >= cnt) return;

    extern __shared__ char smem[];
    uint32_t sA = smem_u32(smem);
    uint32_t sB = sA + H_STG * H_STAGE;

    int tid = threadIdx.x;
    int lane = tid & 31, w = tid >> 5;
    int wm = (w & 3) * 32, wn = (w >> 2) * 64;

    int lrow = tid >> 2;
    int lch  = tid & 3;
    const __half* gA[2]; const __half* gB[2];
    uint32_t stA[2], stB[2];
#pragma unroll
    for (int rr = 0; rr < 2; rr++) {
        int r = lrow + rr * 64;
        int mr = m0 + r;
        int grow = a_idx ? ((mr < cnt) ? a_idx[mr] : 0) : mr;
        gA[rr] = A + (size_t)grow * args.lda + lch * 8;
        gB[rr] = B + (size_t)(n0 + r) * args.ldb + lch * 8;
        stA[rr] = sA + r * HROWB + lch * 16;
        stB[rr] = sB + r * HROWB + lch * 16;
    }

    uint32_t aAddr = sA + (wm + (lane & 15)) * HROWB + ((lane >> 4) & 1) * 16;
    uint32_t bAddr = sB + (wn + (lane & 7) + 8 * ((lane >> 4) & 1)) * HROWB
                        + ((lane >> 3) & 1) * 16;

    float acc[2][8][4];
#pragma unroll
    for (int i = 0; i < 2; i++)
#pragma unroll
        for (int j = 0; j < 8; j++)
#pragma unroll
            for (int q = 0; q < 4; q++) acc[i][j][q] = 0.f;

    int nk = args.K / 32;

#pragma unroll
    for (int s = 0; s < 2; s++) {
#pragma unroll
        for (int rr = 0; rr < 2; rr++) {
            cpa16(stA[rr] + s * H_STAGE, gA[rr] + s * 32);
            cpa16(stB[rr] + s * H_STAGE, gB[rr] + s * 32);
        }
        cpa_commit();
    }

    for (int kt = 0; kt < nk; kt++) {
        cpa_wait1();
        __syncthreads();
        if (kt + 2 < nk) {
            int kb = (kt + 2) * 32;
            uint32_t off = ((kt + 2) % H_STG) * H_STAGE;
#pragma unroll
            for (int rr = 0; rr < 2; rr++) {
                cpa16(stA[rr] + off, gA[rr] + kb);
                cpa16(stB[rr] + off, gB[rr] + kb);
            }
        }
        cpa_commit();

        uint32_t soff = (kt % H_STG) * H_STAGE;
#pragma unroll
        for (int ks = 0; ks < 2; ks++) {
            uint32_t koff = soff + ks * 32;
            uint32_t a[2][4];
            ldsm4(a[0], aAddr + koff);
            ldsm4(a[1], aAddr + koff + 16 * HROWB);
            uint32_t b[4][4];
#pragma unroll
            for (int jp = 0; jp < 4; jp++)
                ldsm4(b[jp], bAddr + koff + jp * (16 * HROWB));
#pragma unroll
            for (int im = 0; im < 2; im++)
#pragma unroll
                for (int jn = 0; jn < 8; jn++)
                    mma16h(acc[im][jn], a[im], b[jn >> 1][(jn & 1) * 2], b[jn >> 1][(jn & 1) * 2 + 1]);
        }
    }

    int cg = 2 * (lane & 3);
#pragma unroll
    for (int im = 0; im < 2; im++) {
#pragma unroll
        for (int half = 0; half < 2; half++) {
            int m = m0 + wm + im * 16 + (lane >> 2) + half * 8;
            if (m >= cnt) continue;
            if (ep_mode == 3) {
                int tr = c_idx[m]; float wv = c_w[m];
                float* cp = Cf + (size_t)tr * args.ldc + n0 + wn + cg;
#pragma unroll
                for (int jn = 0; jn < 8; jn++) {
                    atomicAdd(cp + jn * 8,     wv * acc[im][jn][half * 2 + 0]);
                    atomicAdd(cp + jn * 8 + 1, wv * acc[im][jn][half * 2 + 1]);
                }
            } else if (ep_mode == 1) {
                __half* cp = Ch + (size_t)m * args.ldc + n0 + wn + cg;
#pragma unroll
                for (int jn = 0; jn < 8; jn++)
                    *((__half2*)(cp + jn * 8)) =
                        __floats2half2_rn(acc[im][jn][half * 2 + 0], acc[im][jn][half * 2 + 1]);
            } else if (ep_mode == 2) {
                int bb = m >> 11, ss = m & (S_ - 1);
#pragma unroll
                for (int jn = 0; jn < 8; jn++) {
                    int col = n0 + wn + cg + jn * 8;
                    int hh = col >> 7, d = col & 127;
                    size_t base = ((size_t)(bb * NH_ + hh) * HD_ + d) * S_ + ss;
                    args.H2[base]      = __float2half_rn(acc[im][jn][half * 2 + 0]);
                    args.H2[base + S_] = __float2half_rn(acc[im][jn][half * 2 + 1]);
                }
            } else {
                float* cp = Cf + (size_t)m * args.ldc + n0 + wn + cg;
                if (args.resid) {
                    const float* rp = args.resid + (size_t)m * args.ldc + n0 + wn + cg;
#pragma unroll
                    for (int jn = 0; jn < 8; jn++) {
                        float2 r = *((const float2*)(rp + jn * 8));
                        float2 o;
                        o.x = acc[im][jn][half * 2 + 0] + r.x;
                        o.y = acc[im][jn][half * 2 + 1] + r.y;
                        *((float2*)(cp + jn * 8)) = o;
                    }
                } else {
#pragma unroll
                    for (int jn = 0; jn < 8; jn++) {
                        float2 o;
                        o.x = acc[im][jn][half * 2 + 0];
                        o.y = acc[im][jn][half * 2 + 1];
                        *((float2*)(cp + jn * 8)) = o;
                    }
                }
            }
        }
    }
}

// ==================== causal scores (fp16 pipelined) ====================
__global__ void __launch_bounds__(256, 2)
attn_score_h(const __half* __restrict__ Q, const __half* __restrict__ K16) {
    int bh = blockIdx.z, b = bh >> 4, h = bh & 15;
    int m0 = blockIdx.y * 128, n0 = blockIdx.x * 128;
    if (n0 > m0) return;

    const __half* Qb = Q + (size_t)b * S_ * H_ + h * HD_;
    const __half* Kb = K16 + (size_t)b * S_ * H_ + h * HD_;
    float* Sb = g_att + (size_t)bh * S_ * S_;

    extern __shared__ char smem[];
    uint32_t sA = smem_u32(smem);
    uint32_t sB = sA + H_STG * H_STAGE;

    int tid = threadIdx.x;
    int lane = tid & 31, w = tid >> 5;
    int wm = (w & 3) * 32, wn = (w >> 2) * 64;

    int lrow = tid >> 2, lch = tid & 3;
    const __half* gA[2]; const __half* gB[2];
    uint32_t stA[2], stB[2];
#pragma unroll
    for (int rr = 0; rr < 2; rr++) {
        int r = lrow + rr * 64;
        gA[rr] = Qb + (size_t)(m0 + r) * H_ + lch * 8;
        gB[rr] = Kb + (size_t)(n0 + r) * H_ + lch * 8;
        stA[rr] = sA + r * HROWB + lch * 16;
        stB[rr] = sB + r * HROWB + lch * 16;
    }

    uint32_t aAddr = sA + (wm + (lane & 15)) * HROWB + ((lane >> 4) & 1) * 16;
    uint32_t bAddr = sB + (wn + (lane & 7) + 8 * ((lane >> 4) & 1)) * HROWB
                        + ((lane >> 3) & 1) * 16;

    float acc[2][8][4];
#pragma unroll
    for (int i = 0; i < 2; i++)
#pragma unroll
        for (int j = 0; j < 8; j++)
#pragma unroll
            for (int q = 0; q < 4; q++) acc[i][j][q] = 0.f;

    const int nk = HD_ / 32;

#pragma unroll
    for (int s = 0; s < 2; s++) {
#pragma unroll
        for (int rr = 0; rr < 2; rr++) {
            cpa16(stA[rr] + s * H_STAGE, gA[rr] + s * 32);
            cpa16(stB[rr] + s * H_STAGE, gB[rr] + s * 32);
        }
        cpa_commit();
    }

    for (int kt = 0; kt < nk; kt++) {
        cpa_wait1();
        __syncthreads();
        if (kt + 2 < nk) {
            int kb = (kt + 2) * 32;
            uint32_t off = ((kt + 2) % H_STG) * H_STAGE;
#pragma unroll
            for (int rr = 0; rr < 2; rr++) {
                cpa16(stA[rr] + off, gA[rr] + kb);
                cpa16(stB[rr] + off, gB[rr] + kb);
            }
        }
        cpa_commit();

        uint32_t soff = (kt % H_STG) * H_STAGE;
#pragma unroll
        for (int ks = 0; ks < 2; ks++) {
            uint32_t koff = soff + ks * 32;
            uint32_t a[2][4];
            ldsm4(a[0], aAddr + koff);
            ldsm4(a[1], aAddr + koff + 16 * HROWB);
            uint32_t b2[4][4];
#pragma unroll
            for (int jp = 0; jp < 4; jp++)
                ldsm4(b2[jp], bAddr + koff + jp * (16 * HROWB));
#pragma unroll
            for (int im = 0; im < 2; im++)
#pragma unroll
                for (int jn = 0; jn < 8; jn++)
                    mma16h(acc[im][jn], a[im], b2[jn >> 1][(jn & 1) * 2], b2[jn >> 1][(jn & 1) * 2 + 1]);
        }
    }

    int cg = 2 * (lane & 3);
#pragma unroll
    for (int im = 0; im < 2; im++) {
#pragma unroll
        for (int half = 0; half < 2; half++) {
            int i = m0 + wm + im * 16 + (lane >> 2) + half * 8;
            float* cp = Sb + (size_t)i * S_ + n0 + wn + cg;
#pragma unroll
            for (int jn = 0; jn < 8; jn++) {
                int j = n0 + wn + cg + jn * 8;
                float2 o;
                o.x = (j     > i) ? -1e30f : acc[im][jn][half * 2 + 0] * ATT_SCALE;
                o.y = (j + 1 > i) ? -1e30f : acc[im][jn][half * 2 + 1] * ATT_SCALE;
                *((float2*)(cp + jn * 8)) = o;
            }
        }
    }
}

// ==================== adaptive row softmax: fp32 scores in, fp16 P out ====================
__global__ void softmax_k(__half* __restrict__ P) {
    int r = blockIdx.x & (S_ - 1);
    const float* row = g_att + (size_t)blockIdx.x * S_;
    __half* prow = P + (size_t)blockIdx.x * S_;
    int len = r + 1;
    int tid = threadIdx.x;
    float v[8];
    float mx = -1e30f;
#pragma unroll
    for (int i = 0; i < 8; i++) {
        int j = tid + i * 256;
        v[i] = (j < len) ? row[j] : -1e30f;
        mx = fmaxf(mx, v[i]);
    }
    __shared__ float red[32];
    for (int off = 16; off; off >>= 1) mx = fmaxf(mx, __shfl_xor_sync(0xffffffffu, mx, off));
    if ((tid & 31) == 0) red[tid >> 5] = mx;
    __syncthreads();
    if (tid < 32) {
        float m2 = (tid < 8) ? red[tid] : -1e38f;
        for (int off = 16; off; off >>= 1) m2 = fmaxf(m2, __shfl_xor_sync(0xffffffffu, m2, off));
        if (tid == 0) red[0] = m2;
    }
    __syncthreads();
    mx = red[0];
    float s = 0.f;
#pragma unroll
    for (int i = 0; i < 8; i++) { v[i] = __expf(v[i] - mx); s += v[i]; }
    __syncthreads();
    for (int off = 16; off; off >>= 1) s += __shfl_xor_sync(0xffffffffu, s, off);
    if ((tid & 31) == 0) red[tid >> 5] = s;
    __syncthreads();
    if (tid < 32) {
        float s2 = (tid < 8) ? red[tid] : 0.f;
        for (int off = 16; off; off >>= 1) s2 += __shfl_xor_sync(0xffffffffu, s2, off);
        if (tid == 0) red[0] = s2;
    }
    __syncthreads();
    float inv = 1.f / red[0];
#pragma unroll
    for (int i = 0; i < 8; i++) {
        int j = tid + i * 256;
        if (j < len) prow[j] = __float2half_rn(v[i] * inv);
    }
    int kmax = ((r >> 7) + 1) << 7;
    for (int j = len + tid; j < kmax; j += 256) prow[j] = __float2half_rn(0.f);
}

// ==================== P @ Vt (fp16 pipelined, causal-truncated) ====================
__global__ void __launch_bounds__(256, 2)
attn_pv_h(const __half* __restrict__ P, const __half* __restrict__ Vt,
          __half* __restrict__ O) {
    int bh = blockIdx.y, b = bh >> 4, h = bh & 15;
    int m0 = blockIdx.x * 128;
    const __half* Pb = P + (size_t)bh * S_ * S_;
    const __half* Vb = Vt + (size_t)bh * HD_ * S_;

    extern __shared__ char smem[];
    uint32_t sA = smem_u32(smem);
    uint32_t sB = sA + H_STG * H_STAGE;

    int tid = threadIdx.x;
    int lane = tid & 31, w = tid >> 5;
    int wm = (w & 3) * 32, wn = (w >> 2) * 64;

    int lrow = tid >> 2, lch = tid & 3;
    const __half* gA[2]; const __half* gB[2];
    uint32_t stA[2], stB[2];
#pragma unroll
    for (int rr = 0; rr < 2; rr++) {
        int r = lrow + rr * 64;
        gA[rr] = Pb + (size_t)(m0 + r) * S_ + lch * 8;
        gB[rr] = Vb + (size_t)r * S_ + lch * 8;
        stA[rr] = sA + r * HROWB + lch * 16;
        stB[rr] = sB + r * HROWB + lch * 16;
    }

    uint32_t aAddr = sA + (wm + (lane & 15)) * HROWB + ((lane >> 4) & 1) * 16;
    uint32_t bAddr = sB + (wn + (lane & 7) + 8 * ((lane >> 4) & 1)) * HROWB
                        + ((lane >> 3) & 1) * 16;

    float acc[2][8][4];
#pragma unroll
    for (int i = 0; i < 2; i++)
#pragma unroll
        for (int j = 0; j < 8; j++)
#pragma unroll
            for (int q = 0; q < 4; q++) acc[i][j][q] = 0.f;

    int nk = (m0 + 128) / 32;

#pragma unroll
    for (int s = 0; s < 2; s++) {
#pragma unroll
        for (int rr = 0; rr < 2; rr++) {
            cpa16(stA[rr] + s * H_STAGE, gA[rr] + s * 32);
            cpa16(stB[rr] + s * H_STAGE, gB[rr] + s * 32);
        }
        cpa_commit();
    }

    for (int kt = 0; kt < nk; kt++) {
        cpa_wait1();
        __syncthreads();
        if (kt + 2 < nk) {
            int kb = (kt + 2) * 32;
            uint32_t off = ((kt + 2) % H_STG) * H_STAGE;
#pragma unroll
            for (int rr = 0; rr < 2; rr++) {
                cpa16(stA[rr] + off, gA[rr] + kb);
                cpa16(stB[rr] + off, gB[rr] + kb);
            }
        }
        cpa_commit();

        uint32_t soff = (kt % H_STG) * H_STAGE;
#pragma unroll
        for (int ks = 0; ks < 2; ks++) {
            uint32_t koff = soff + ks * 32;
            uint32_t a[2][4];
            ldsm4(a[0], aAddr + koff);
            ldsm4(a[1], aAddr + koff + 16 * HROWB);
            uint32_t b2[4][4];
#pragma unroll
            for (int jp = 0; jp < 4; jp++)
                ldsm4(b2[jp], bAddr + koff + jp * (16 * HROWB));
#pragma unroll
            for (int im = 0; im < 2; im++)
#pragma unroll
                for (int jn = 0; jn < 8; jn++)
                    mma16h(acc[im][jn], a[im], b2[jn >> 1][(jn & 1) * 2], b2[jn >> 1][(jn & 1) * 2 + 1]);
        }
    }

    int cg = 2 * (lane & 3);
#pragma unroll
    for (int im = 0; im < 2; im++) {
#pragma unroll
        for (int half = 0; half < 2; half++) {
            int m = m0 + wm + im * 16 + (lane >> 2) + half * 8;
            __half* cp = O + (size_t)(b * S_ + m) * H_ + h * HD_ + wn + cg;
#pragma unroll
            for (int jn = 0; jn < 8; jn++)
                *((__half2*)(cp + jn * 8)) =
                    __floats2half2_rn(acc[im][jn][half * 2 + 0], acc[im][jn][half * 2 + 1]);
        }
    }
}

// ==================== router (EXACT fp32 input) ====================
__global__ void router_k(const float* __restrict__ xn2e, const float* __restrict__ Wr) {
    int t = blockIdx.x * (blockDim.x >> 5) + (threadIdx.x >> 5);
    if (t >= T_) return;
    int lane = threadIdx.x & 31;
    const float* xr = xn2e + (size_t)t * H_;
    float s[NE_];
#pragma unroll
    for (int e = 0; e < NE_; e++) s[e] = 0.f;
    for (int j = lane; j < H_; j += 32) {
        float xv = xr[j];
#pragma unroll
        for (int e = 0; e < NE_; e++) s[e] += xv * Wr[e * H_ + j];
    }
#pragma unroll
    for (int e = 0; e < NE_; e++)
        for (int off = 16; off; off >>= 1) s[e] += __shfl_xor_sync(0xffffffffu, s[e], off);
    if (lane == 0) {
        int b0 = 0;
#pragma unroll
        for (int e = 1; e < NE_; e++) if (s[e] > s[b0]) b0 = e;
        int b1 = -1;
#pragma unroll
        for (int e = 0; e < NE_; e++) {
            if (e == b0) continue;
            if (b1 < 0 || s[e] > s[b1]) b1 = e;
        }
        float m = s[b0];
        float e0 = __expf(s[b0] - m), e1 = __expf(s[b1] - m);
        float inv = 1.f / (e0 + e1);
        int pos = atomicAdd(&g_cnt[b0], 1);
        g_tok[b0 * T_ + pos] = t; g_wt[b0 * T_ + pos] = e0 * inv;
        pos = atomicAdd(&g_cnt[b1], 1);
        g_tok[b1 * T_ + pos] = t; g_wt[b1 * T_ + pos] = e1 * inv;
    }
}

// ==================== host ====================
extern "C" void kernel_launch(void* const* d_in, const int* in_sizes, int n_in,
                              void* d_out, int out_size) {
    const float* x    = (const float*)d_in[0];
    const float* Wq   = (const float*)d_in[1];
    const float* Wk   = (const float*)d_in[2];
    const float* Wv   = (const float*)d_in[3];
    const float* Wo   = (const float*)d_in[4];
    const float* wln1 = (const float*)d_in[5];
    const float* wln2 = (const float*)d_in[6];
    const float* Wr   = (const float*)d_in[7];
    const float* Wg   = (const float*)d_in[8];
    const float* Wu   = (const float*)d_in[9];
    const float* Wd   = (const float*)d_in[10];
    float* out = (float*)d_out;

    float *p_hg, *p_rex, *p_wt;
    __half *p_q16, *p_k16, *p_vt16, *p_xn16, *p_ao16, *p_xn216, *p_hg16, *p_w16;
    int *p_tok, *p_cnt;
    cudaGetSymbolAddress((void**)&p_hg,    g_hg);
    cudaGetSymbolAddress((void**)&p_rex,   g_rex);
    cudaGetSymbolAddress((void**)&p_q16,   g_q16);
    cudaGetSymbolAddress((void**)&p_k16,   g_k16);
    cudaGetSymbolAddress((void**)&p_vt16,  g_vt16);
    cudaGetSymbolAddress((void**)&p_xn16,  g_xn16);
    cudaGetSymbolAddress((void**)&p_ao16,  g_ao16);
    cudaGetSymbolAddress((void**)&p_xn216, g_xn216);
    cudaGetSymbolAddress((void**)&p_hg16,  g_hg16);
    cudaGetSymbolAddress((void**)&p_w16,   g_w16);
    cudaGetSymbolAddress((void**)&p_tok,   g_tok);
    cudaGetSymbolAddress((void**)&p_wt,    g_wt);
    cudaGetSymbolAddress((void**)&p_cnt,   g_cnt);

    __half* p_P = (__half*)p_hg;
    __half* p_hgpre = (__half*)p_hg;
    __half* p_hupre = (__half*)p_hg + (size_t)NE_ * T_ * I_;

    static int inited = 0;
    static cudaStream_t s2;
    static cudaEvent_t ev_fork, ev_wo, ev_moe;
    if (!inited) {
        cudaFuncSetAttribute(hgemm, cudaFuncAttributeMaxDynamicSharedMemorySize, H_SMEM);
        cudaFuncSetAttribute(attn_score_h, cudaFuncAttributeMaxDynamicSharedMemorySize, H_SMEM);
        cudaFuncSetAttribute(attn_pv_h, cudaFuncAttributeMaxDynamicSharedMemorySize, H_SMEM);
        cudaStreamCreateWithFlags(&s2, cudaStreamNonBlocking);
        cudaEventCreateWithFlags(&ev_fork, cudaEventDisableTiming);
        cudaEventCreateWithFlags(&ev_wo,   cudaEventDisableTiming);
        cudaEventCreateWithFlags(&ev_moe,  cudaEventDisableTiming);
        inited = 1;
    }

    zero_cnt_k<<<1, 32>>>();

    // main stream: weights needed first
    cvt16_k<<<1024, 256>>>(Wq, p_w16 + OFF_WQ, (size_t)H_ * H_ / 8);
    cvt16_k<<<1024, 256>>>(Wk, p_w16 + OFF_WK, (size_t)H_ * H_ / 8);
    cvt16_k<<<1024, 256>>>(Wv, p_w16 + OFF_WV, (size_t)H_ * H_ / 8);

    // fork: remaining weight conversions overlap with attention phase
    cudaEventRecord(ev_fork, 0);
    cudaStreamWaitEvent(s2, ev_fork, 0);
    cvt16_k<<<1024, 256, 0, s2>>>(Wo, p_w16 + OFF_WO, (size_t)H_ * H_ / 8);
    cudaEventRecord(ev_wo, s2);
    cvt16_k<<<4096, 256, 0, s2>>>(Wg, p_w16 + OFF_WG, (size_t)NE_ * I_ * H_ / 8);
    cvt16_k<<<4096, 256, 0, s2>>>(Wu, p_w16 + OFF_WU, (size_t)NE_ * I_ * H_ / 8);
    cvt16_k<<<4096, 256, 0, s2>>>(Wd, p_w16 + OFF_WD, (size_t)NE_ * H_ * I_ / 8);
    cudaEventRecord(ev_moe, s2);

    rmsnorm_k<<<T_, 256>>>(x, wln1, p_xn16, nullptr);

    // QKV fused: q,k -> fp16 [t][H]; v -> fp16 transposed [b,h][d][s]
    {
        GArgs a = {};
        a.A = p_xn16;
        a.B0 = p_w16 + OFF_WQ; a.B1 = p_w16 + OFF_WK; a.B2 = p_w16 + OFF_WV;
        a.H0 = p_q16; a.H1 = p_k16; a.H2 = p_vt16;
        a.M = T_; a.N = H_; a.K = H_; a.lda = H_; a.ldb = H_; a.ldc = H_;
        a.mode = 0; a.qkv = 1;
        hgemm<<<dim3(H_ / 128, T_ / 128, 3), 256, H_SMEM>>>(a);
    }

    attn_score_h<<<dim3(S_ / 128, S_ / 128, B_ * NH_), 256, H_SMEM>>>(p_q16, p_k16);
    softmax_k<<<B_ * NH_ * S_, 256>>>(p_P);
    attn_pv_h<<<dim3(S_ / 128, B_ * NH_), 256, H_SMEM>>>(p_P, p_vt16, p_ao16);

    // join: Wo fp16 ready
    cudaStreamWaitEvent(0, ev_wo, 0);

    // Wo projection + fused residual (fp32 out)
    {
        GArgs a = {};
        a.A = p_ao16; a.B0 = p_w16 + OFF_WO; a.C0 = out;
        a.resid = x;
        a.M = T_; a.N = H_; a.K = H_; a.lda = H_; a.ldb = H_; a.ldc = H_;
        a.mode = 0;
        hgemm<<<dim3(H_ / 128, T_ / 128, 1), 256, H_SMEM>>>(a);
    }

    rmsnorm_k<<<T_, 256>>>(out, wln2, p_xn216, p_rex);
    router_k<<<T_ / 8, 256>>>(p_rex, Wr);

    // join: MoE weights fp16 ready
    cudaStreamWaitEvent(0, ev_moe, 0);

    // MoE gate+up (gathered A; fp16 pre-act outputs)
    {
        GArgs a = {};
        a.A = p_xn216;
        a.B0 = p_w16 + OFF_WG; a.B1 = p_w16 + OFF_WU;
        a.H0 = p_hgpre; a.H1 = p_hupre;
        a.M = T_; a.N = I_; a.K = H_; a.lda = H_; a.ldb = H_; a.ldc = I_;
        a.tok = p_tok; a.cntp = p_cnt;
        a.bStride = (size_t)I_ * H_; a.cStride = (size_t)T_ * I_;
        a.mode = 1;
        hgemm<<<dim3(I_ / 128, T_ / 128, 2 * NE_), 256, H_SMEM>>>(a);
    }

    swiglu_all_k<<<dim3(512, NE_), 256>>>(p_hgpre, p_hupre, p_hg16);

    // MoE down: atomic scatter-add into out
    {
        GArgs a = {};
        a.A = p_hg16; a.B0 = p_w16 + OFF_WD; a.C0 = out;
        a.M = T_; a.N = H_; a.K = I_; a.lda = I_; a.ldb = I_; a.ldc = H_;
        a.tok = p_tok; a.wt = p_wt; a.cntp = p_cnt;
        a.aStride = (size_t)T_ * I_; a.bStride = (size_t)H_ * I_;
        a.mode = 2;
        hgemm<<<dim3(H_ / 128, T_ / 128, NE_), 256, H_SMEM>>>(a);
    }
}